// round 11
// baseline (speedup 1.0000x reference)
#include <cuda_runtime.h>
#include <cuda_bf16.h>
#include <cstdint>

typedef __nv_bfloat16 bf16;
#define THREADS 512
#define LOG_SQRT_2PI 0.9189385332046727f

// ---------- packed weights: per (16k x 8n) block, 256 bf16 (B-frag order, hi+lo) ----------
__device__ bf16 g_wpack[2789376];   // 10896 blocks * 256

struct LDesc { int K, N, base, sid, soff; };
__constant__ LDesc c_layers[25] = {
    {256,512,0,0,0},{512,256,1024,1,0},
    {256,256,2048,2,0},{256,256,2560,2,65536},{256,256,3072,2,131072},{256,256,3584,2,196608},
    {256,256,4096,2,262144},{256,256,4608,2,327680},{256,256,5120,2,393216},{256,256,5632,2,458752},
    {256,40,6144,3,0},{256,40,6224,3,10240},{256,40,6304,3,20480},{256,40,6384,3,30720},
    {256,40,6464,3,40960},{256,40,6544,3,51200},{256,40,6624,3,61440},{256,40,6704,3,71680},
    {256,512,6784,4,0},{512,256,7808,5,0},{256,128,8832,6,0},
    {128,512,9088,7,0},{512,256,9600,8,0},{256,128,10624,9,0},
    {256,8,10880,10,0}
};
__constant__ long c_prefix[26] = {
    0,131072,262144,327680,393216,458752,524288,589824,655360,720896,786432,
    796672,806912,817152,827392,837632,847872,858112,868352,
    999424,1130496,1163264,1228800,1359872,1392640,1394688
};

struct PrepArgs { const float* s[11]; };

__global__ void prep_kernel(PrepArgs a) {
    long i = (long)blockIdx.x * 256 + threadIdx.x;
    if (i >= 1394688L) return;
    int L = 0;
    while (c_prefix[L + 1] <= i) L++;
    LDesc d = c_layers[L];
    int e = (int)(i - c_prefix[L]);
    int k = e / d.N, n = e % d.N;
    float w = a.s[d.sid][(size_t)d.soff + e];
    bf16 hi = __float2bfloat16(w);
    bf16 lo = __float2bfloat16(w - __bfloat162float(hi));
    int blk = d.base + (n >> 3) * (d.K >> 4) + (k >> 4);
    int r = k & 15;
    int lane = (n & 7) * 4 + ((r & 7) >> 1);
    int sub = (r & 1) + ((r >= 8) ? 2 : 0);
    bf16* dst = g_wpack + (long)blk * 256 + lane * 8;
    dst[sub] = hi;
    dst[sub + 4] = lo;
}

// ---------- main kernel helpers ----------
__device__ __forceinline__ uint32_t s2u(const void* p) {
    return (uint32_t)__cvta_generic_to_shared(p);
}
__device__ __forceinline__ void ldsm4(uint32_t a, uint32_t* r) {
    asm volatile("ldmatrix.sync.aligned.m8n8.x4.shared.b16 {%0,%1,%2,%3}, [%4];"
        : "=r"(r[0]), "=r"(r[1]), "=r"(r[2]), "=r"(r[3]) : "r"(a));
}
__device__ __forceinline__ void hmma(float* d, const uint32_t* a, uint32_t b0, uint32_t b1) {
    asm volatile("mma.sync.aligned.m16n8k16.row.col.f32.bf16.bf16.f32 "
        "{%0,%1,%2,%3}, {%4,%5,%6,%7}, {%8,%9}, {%0,%1,%2,%3};"
        : "+f"(d[0]), "+f"(d[1]), "+f"(d[2]), "+f"(d[3])
        : "r"(a[0]), "r"(a[1]), "r"(a[2]), "r"(a[3]), "r"(b0), "r"(b1));
}
__device__ __forceinline__ float lrelu(float v) { return v > 0.f ? v : 0.01f * v; }
__device__ __forceinline__ void zeroD(float D[4][4]) {
#pragma unroll
    for (int j = 0; j < 4; j++)
#pragma unroll
        for (int i = 0; i < 4; i++) D[j][i] = 0.f;
}

// D[j] += A(region) @ B(ntile = wc + 8j), k-tiles 0..KT-1.  (round-9 schedule)
template <int NTW, int KT>
__device__ __forceinline__ void mma_pass(
    float D[4][4], int blkBase, int ktStride,
    uint32_t aHiA, uint32_t aLoA, int sp, int mt, int wc, int lane)
{
    uint32_t off = (uint32_t)(((mt * 16 + (lane & 15)) * sp + (lane >> 4) * 8) * 2);
    uint32_t ah0 = aHiA + off, al0 = aLoA + off;
    const uint4* bp[NTW];
#pragma unroll
    for (int j = 0; j < NTW; j++)
        bp[j] = reinterpret_cast<const uint4*>(
                    g_wpack + (long)(blkBase + (wc + 8 * j) * ktStride) * 256) + lane;
    uint4 bc[NTW];
#pragma unroll
    for (int j = 0; j < NTW; j++) bc[j] = bp[j][0];
#pragma unroll 1
    for (int kt = 0; kt < KT; kt++) {
        uint32_t ah[4], al[4];
        ldsm4(ah0 + kt * 32, ah);
        ldsm4(al0 + kt * 32, al);
        uint4 bn[NTW];
        if (kt + 1 < KT) {
#pragma unroll
            for (int j = 0; j < NTW; j++) bn[j] = bp[j][(kt + 1) * 32];
        }
#pragma unroll
        for (int j = 0; j < NTW; j++) {
            hmma(D[j], ah, bc[j].x, bc[j].y);   // Ahi*Bhi
            hmma(D[j], ah, bc[j].z, bc[j].w);   // Ahi*Blo
            hmma(D[j], al, bc[j].x, bc[j].y);   // Alo*Bhi
        }
#pragma unroll
        for (int j = 0; j < NTW; j++) bc[j] = bn[j];
    }
}

// epilogue: +bias (+lrelu) -> hi/lo bf16 region
template <int NTW, bool RELU>
__device__ __forceinline__ void epi_bf(
    float D[4][4], const float* bias, bf16* dHi, bf16* dLo,
    int sp, int mt, int wc, int lane)
{
    int r0 = lane >> 2, c0 = (lane & 3) * 2;
#pragma unroll
    for (int j = 0; j < NTW; j++) {
        int col = (wc + 8 * j) * 8 + c0;
        float b0 = bias[col], b1 = bias[col + 1];
#pragma unroll
        for (int h = 0; h < 2; h++) {
            int row = mt * 16 + r0 + h * 8;
            float v0 = D[j][2 * h] + b0, v1 = D[j][2 * h + 1] + b1;
            if (RELU) { v0 = lrelu(v0); v1 = lrelu(v1); }
            bf16 h0 = __float2bfloat16(v0), h1 = __float2bfloat16(v1);
            bf16 g0 = __float2bfloat16(v0 - __bfloat162float(h0));
            bf16 g1 = __float2bfloat16(v1 - __bfloat162float(h1));
            *(uint32_t*)(dHi + row * sp + col) =
                ((uint32_t)__bfloat16_as_ushort(h1) << 16) | __bfloat16_as_ushort(h0);
            *(uint32_t*)(dLo + row * sp + col) =
                ((uint32_t)__bfloat16_as_ushort(g1) << 16) | __bfloat16_as_ushort(g0);
        }
    }
}

// smem byte offsets
#define O_RINH 0
#define O_RINL 16896
#define O_RGLH 33792
#define O_RGLL 42496
#define O_RAH  51200
#define O_RAL  84480
#define O_RBH  117760
#define O_RBL  134656
#define O_RCH  151552
#define O_RCL  168448
#define O_GATE 185344
#define O_SUM1 186368
#define O_SUM2 188928
#define O_ACT  191488
#define O_PS0  194048
#define O_PS1  199680
#define SMEM_BYTES 205312
// p-loop: second h buffer overlays dead RIN region
#define O_RC2H O_RINH
#define O_RC2L O_RINL

__global__ __launch_bounds__(THREADS, 1) void actor_kernel(
    const float* __restrict__ obs, const float* __restrict__ actions,
    const float* __restrict__ b1, const float* __restrict__ b2,
    const float* __restrict__ bp1, const float* __restrict__ bp2,
    const float* __restrict__ bs1, const float* __restrict__ bs2,
    const float* __restrict__ bs3, const float* __restrict__ bg1,
    const float* __restrict__ bg2, const float* __restrict__ bg3,
    const float* __restrict__ bgate,
    float* __restrict__ out)
{
    extern __shared__ char sm[];
    bf16* RINh = (bf16*)(sm + O_RINH); bf16* RINl = (bf16*)(sm + O_RINL);
    bf16* RGLh = (bf16*)(sm + O_RGLH); bf16* RGLl = (bf16*)(sm + O_RGLL);
    bf16* RAh  = (bf16*)(sm + O_RAH);  bf16* RAl  = (bf16*)(sm + O_RAL);
    bf16* RBh  = (bf16*)(sm + O_RBH);  bf16* RBl  = (bf16*)(sm + O_RBL);
    bf16* RCh  = (bf16*)(sm + O_RCH);  bf16* RCl  = (bf16*)(sm + O_RCL);
    bf16* RC2h = (bf16*)(sm + O_RC2H); bf16* RC2l = (bf16*)(sm + O_RC2L);
    float* sGate = (float*)(sm + O_GATE);
    float* sSum1 = (float*)(sm + O_SUM1);
    float* sSum2 = (float*)(sm + O_SUM2);
    float* sAct  = (float*)(sm + O_ACT);
    float* sPS[2] = { (float*)(sm + O_PS0), (float*)(sm + O_PS1) };

    const uint32_t RINhA = s2u(RINh), RINlA = s2u(RINl);
    const uint32_t RGLhA = s2u(RGLh), RGLlA = s2u(RGLl);
    const uint32_t RAhA  = s2u(RAh),  RAlA  = s2u(RAl);
    const uint32_t RBhA  = s2u(RBh),  RBlA  = s2u(RBl);
    const uint32_t RChA  = s2u(RCh),  RClA  = s2u(RCl);
    const uint32_t RC2hA = s2u(RC2h), RC2lA = s2u(RC2l);

    const int t = threadIdx.x;
    const int lane = t & 31, w = t >> 5;
    const int mt = w & 1, wc = w >> 1;
    const int rowBase = blockIdx.x * 32;

    // ---- inputs -> hi/lo bf16, misc staging ----
    for (int i = t; i < 32 * 96; i += THREADS) {
        int b = i / 96, c4 = i % 96;
        float4 v = *reinterpret_cast<const float4*>(obs + (size_t)(rowBase + b) * 384 + c4 * 4);
        bf16 *ph, *pl;
        int c;
        if (c4 < 64) { c = c4 * 4; ph = RINh + b * 264 + c; pl = RINl + b * 264 + c; }
        else         { c = (c4 - 64) * 4; ph = RGLh + b * 136 + c; pl = RGLl + b * 136 + c; }
        float vv[4] = {v.x, v.y, v.z, v.w};
#pragma unroll
        for (int q = 0; q < 4; q++) {
            bf16 h = __float2bfloat16(vv[q]);
            ph[q] = h;
            pl[q] = __float2bfloat16(vv[q] - __bfloat162float(h));
        }
    }
    for (int i = t; i < 640; i += THREADS) {
        sAct[i] = actions[(size_t)rowBase * 20 + i];
        sSum1[i] = 0.f; sSum2[i] = 0.f;
    }
    __syncthreads();

    float D[4][4];
    // ---- gate path ----
    zeroD(D); mma_pass<4,16>(D, 6784,      16, RINhA, RINlA, 264, mt, wc, lane);
    epi_bf<4,true>(D, bs1,       RAh,       RAl,       520, mt, wc, lane);
    zeroD(D); mma_pass<4,16>(D, 6784+512,  16, RINhA, RINlA, 264, mt, wc, lane);
    epi_bf<4,true>(D, bs1 + 256, RAh + 256, RAl + 256, 520, mt, wc, lane);
    __syncthreads();
    zeroD(D); mma_pass<4,32>(D, 7808, 32, RAhA, RAlA, 520, mt, wc, lane);
    epi_bf<4,true>(D, bs2, RBh, RBl, 264, mt, wc, lane);
    __syncthreads();
    zeroD(D); mma_pass<2,16>(D, 8832, 16, RBhA, RBlA, 264, mt, wc, lane);
    epi_bf<2,true>(D, bs3, RCh, RCl, 264, mt, wc, lane);      // sg[:,0:128]
    zeroD(D); mma_pass<4,8>(D, 9088,      8, RGLhA, RGLlA, 136, mt, wc, lane);
    epi_bf<4,true>(D, bg1,       RAh,       RAl,       520, mt, wc, lane);
    zeroD(D); mma_pass<4,8>(D, 9088+256,  8, RGLhA, RGLlA, 136, mt, wc, lane);
    epi_bf<4,true>(D, bg1 + 256, RAh + 256, RAl + 256, 520, mt, wc, lane);
    __syncthreads();
    zeroD(D); mma_pass<4,32>(D, 9600, 32, RAhA, RAlA, 520, mt, wc, lane);
    epi_bf<4,true>(D, bg2, RBh, RBl, 264, mt, wc, lane);
    __syncthreads();
    zeroD(D); mma_pass<2,16>(D, 10624, 16, RBhA, RBlA, 264, mt, wc, lane);
    epi_bf<2,true>(D, bg3, RCh + 128, RCl + 128, 264, mt, wc, lane);  // sg[:,128:256]
    __syncthreads();

    // ---- gate as MMA layer: w_gate = exp(sg @ Wgate + bgate) (warps wc==0) ----
    if (wc == 0) {
        zeroD(D); mma_pass<1,16>(D, 10880, 16, RChA, RClA, 264, mt, 0, lane);
        int r0 = lane >> 2, c0 = (lane & 3) * 2;
        float g0 = bgate[c0], g1 = bgate[c0 + 1];
#pragma unroll
        for (int h = 0; h < 2; h++) {
            int row = mt * 16 + r0 + h * 8;
            sGate[row * 8 + c0]     = expf(D[0][2 * h]     + g0);
            sGate[row * 8 + c0 + 1] = expf(D[0][2 * h + 1] + g1);
        }
    }

    // ---- primitive trunk (other warps proceed concurrently with gate) ----
    zeroD(D); mma_pass<4,16>(D, 0,   16, RINhA, RINlA, 264, mt, wc, lane);
    epi_bf<4,true>(D, b1,       RAh,       RAl,       520, mt, wc, lane);
    zeroD(D); mma_pass<4,16>(D, 512, 16, RINhA, RINlA, 264, mt, wc, lane);
    epi_bf<4,true>(D, b1 + 256, RAh + 256, RAl + 256, 520, mt, wc, lane);
    __syncthreads();
    zeroD(D); mma_pass<4,32>(D, 1024, 32, RAhA, RAlA, 520, mt, wc, lane);
    epi_bf<4,true>(D, b2, RBh, RBl, 264, mt, wc, lane);   // s1 stays in RB
    __syncthreads();
    // RIN/RGL dead from here: RC2 overlays them.

    for (int p = 0; p < 8; p++) {
        const int pb = p & 1;
        bf16* Ch = pb ? RC2h : RCh;  bf16* Cl = pb ? RC2l : RCl;
        const uint32_t ChA = pb ? RC2hA : RChA;
        const uint32_t ClA = pb ? RC2lA : RClA;

        // phase A: h(p) = lrelu(s1 @ Wp1[p] + bp1[p])  (all 16 warps)
        zeroD(D); mma_pass<4,16>(D, 2048 + p * 512, 16, RBhA, RBlA, 264, mt, wc, lane);
        epi_bf<4,true>(D, bp1 + p * 256, Ch, Cl, 264, mt, wc, lane);
        __syncthreads();

        // phase B: warps 0-9 do Wp2(p); warps 10-15 do mixture(p-1)
        if (wc < 5) {
            zeroD(D); mma_pass<1,16>(D, 6144 + p * 80, 16, ChA, ClA, 264, mt, wc, lane);
            int r0 = lane >> 2, c0 = (lane & 3) * 2;
            int col = wc * 8 + c0;
            float bb0 = bp2[p * 40 + col], bb1 = bp2[p * 40 + col + 1];
            float* PS = sPS[pb];
#pragma unroll
            for (int h = 0; h < 2; h++) {
                int row = mt * 16 + r0 + h * 8;
                PS[row * 44 + col]     = D[0][2 * h]     + bb0;
                PS[row * 44 + col + 1] = D[0][2 * h + 1] + bb1;
            }
        } else if (p > 0) {
            const float* PS = sPS[pb ^ 1];
            const float gscale = 1.f;
            for (int i = t - 320; i < 640; i += 192) {
                int b = i / 20, a = i % 20;
                float mu  = PS[b * 44 + a];
                float sig = expf(PS[b * 44 + 20 + a]);
                float inv = sGate[b * 8 + (p - 1)] / sig;
                sSum1[i] += mu * inv * gscale;
                sSum2[i] += inv;
            }
        }
        __syncthreads();
    }

    // mixture for p=7 (all threads)
    for (int i = t; i < 640; i += THREADS) {
        int b = i / 20, a = i % 20;
        float mu  = sPS[1][b * 44 + a];
        float sig = expf(sPS[1][b * 44 + 20 + a]);
        float inv = sGate[b * 8 + 7] / sig;
        sSum1[i] += mu * inv;
        sSum2[i] += inv;
    }
    __syncthreads();

    // ---- final log_prob / entropy ----
    if (t < 32) {
        int b = t;
        float lp = 0.f, ent = 0.f;
#pragma unroll
        for (int a = 0; a < 20; a++) {
            float s1v = sSum1[b * 20 + a];
            float s2v = sSum2[b * 20 + a];
            float mu = s1v / s2v;
            float z = (sAct[b * 20 + a] - mu) * s2v;
            float ls = -logf(s2v);
            lp  += -0.5f * z * z - ls - LOG_SQRT_2PI;
            ent += 0.5f + LOG_SQRT_2PI + ls;
        }
        size_t row = (size_t)rowBase + b;
        out[row * 2 + 0] = lp;
        out[row * 2 + 1] = ent;
    }
}

extern "C" void kernel_launch(void* const* d_in, const int* in_sizes, int n_in,
                              void* d_out, int out_size)
{
    PrepArgs pa;
    pa.s[0] = (const float*)d_in[2];   // W1
    pa.s[1] = (const float*)d_in[4];   // W2
    pa.s[2] = (const float*)d_in[6];   // Wp1
    pa.s[3] = (const float*)d_in[8];   // Wp2
    pa.s[4] = (const float*)d_in[10];  // Ws1
    pa.s[5] = (const float*)d_in[12];  // Ws2
    pa.s[6] = (const float*)d_in[14];  // Ws3
    pa.s[7] = (const float*)d_in[16];  // Wg1
    pa.s[8] = (const float*)d_in[18];  // Wg2
    pa.s[9] = (const float*)d_in[20];  // Wg3
    pa.s[10] = (const float*)d_in[22]; // Wgate
    prep_kernel<<<(1394688 + 255) / 256, 256>>>(pa);

    cudaFuncSetAttribute(actor_kernel,
                         cudaFuncAttributeMaxDynamicSharedMemorySize, SMEM_BYTES);
    actor_kernel<<<2048, THREADS, SMEM_BYTES>>>(
        (const float*)d_in[0], (const float*)d_in[1],
        (const float*)d_in[3], (const float*)d_in[5],
        (const float*)d_in[7], (const float*)d_in[9],
        (const float*)d_in[11], (const float*)d_in[13],
        (const float*)d_in[15], (const float*)d_in[17],
        (const float*)d_in[19], (const float*)d_in[21],
        (const float*)d_in[23],
        (float*)d_out);
}

// round 12
// speedup vs baseline: 1.4951x; 1.4951x over previous
#include <cuda_runtime.h>
#include <cuda_bf16.h>
#include <cstdint>

typedef __nv_bfloat16 bf16;
#define THREADS 256
#define LOG_SQRT_2PI 0.9189385332046727f

// ---------- packed weights: per (16k x 8n) block, 256 bf16 (B-frag order, hi+lo) ----------
__device__ bf16 g_wpack[2785280];   // 10880 blocks * 256

struct LDesc { int K, N, base, sid, soff; };
__constant__ LDesc c_layers[24] = {
    {256,512,0,0,0},{512,256,1024,1,0},
    {256,256,2048,2,0},{256,256,2560,2,65536},{256,256,3072,2,131072},{256,256,3584,2,196608},
    {256,256,4096,2,262144},{256,256,4608,2,327680},{256,256,5120,2,393216},{256,256,5632,2,458752},
    {256,40,6144,3,0},{256,40,6224,3,10240},{256,40,6304,3,20480},{256,40,6384,3,30720},
    {256,40,6464,3,40960},{256,40,6544,3,51200},{256,40,6624,3,61440},{256,40,6704,3,71680},
    {256,512,6784,4,0},{512,256,7808,5,0},{256,128,8832,6,0},
    {128,512,9088,7,0},{512,256,9600,8,0},{256,128,10624,9,0}
};
__constant__ long c_prefix[25] = {
    0,131072,262144,327680,393216,458752,524288,589824,655360,720896,786432,
    796672,806912,817152,827392,837632,847872,858112,868352,
    999424,1130496,1163264,1228800,1359872,1392640
};

struct PrepArgs { const float* s[10]; };

__global__ void prep_kernel(PrepArgs a) {
    long i = (long)blockIdx.x * 256 + threadIdx.x;
    if (i >= 1392640L) return;
    int L = 0;
    while (c_prefix[L + 1] <= i) L++;
    LDesc d = c_layers[L];
    int e = (int)(i - c_prefix[L]);
    int k = e / d.N, n = e % d.N;
    float w = a.s[d.sid][(size_t)d.soff + e];
    bf16 hi = __float2bfloat16(w);
    bf16 lo = __float2bfloat16(w - __bfloat162float(hi));
    int blk = d.base + (n >> 3) * (d.K >> 4) + (k >> 4);
    int r = k & 15;
    int lane = (n & 7) * 4 + ((r & 7) >> 1);
    int sub = (r & 1) + ((r >= 8) ? 2 : 0);
    bf16* dst = g_wpack + (long)blk * 256 + lane * 8;
    dst[sub] = hi;
    dst[sub + 4] = lo;
}

// ---------- main kernel helpers ----------
__device__ __forceinline__ uint32_t s2u(const void* p) {
    return (uint32_t)__cvta_generic_to_shared(p);
}
__device__ __forceinline__ void ldsm4(uint32_t a, uint32_t* r) {
    asm volatile("ldmatrix.sync.aligned.m8n8.x4.shared.b16 {%0,%1,%2,%3}, [%4];"
        : "=r"(r[0]), "=r"(r[1]), "=r"(r[2]), "=r"(r[3]) : "r"(a));
}
__device__ __forceinline__ void hmma(float* d, const uint32_t* a, uint32_t b0, uint32_t b1) {
    asm volatile("mma.sync.aligned.m16n8k16.row.col.f32.bf16.bf16.f32 "
        "{%0,%1,%2,%3}, {%4,%5,%6,%7}, {%8,%9}, {%0,%1,%2,%3};"
        : "+f"(d[0]), "+f"(d[1]), "+f"(d[2]), "+f"(d[3])
        : "r"(a[0]), "r"(a[1]), "r"(a[2]), "r"(a[3]), "r"(b0), "r"(b1));
}
__device__ __forceinline__ float lrelu(float v) { return v > 0.f ? v : 0.01f * v; }
__device__ __forceinline__ void zeroD(float D[4][4]) {
#pragma unroll
    for (int j = 0; j < 4; j++)
#pragma unroll
        for (int i = 0; i < 4; i++) D[j][i] = 0.f;
}

// D[j] += A(region, 16 rows) @ B(ntile = wc + 8j), k-tiles 0..KT-1.  (round-9 schedule)
template <int NTW, int KT>
__device__ __forceinline__ void mma_pass(
    float D[4][4], int blkBase, int ktStride,
    uint32_t aHiA, uint32_t aLoA, int sp, int wc, int lane)
{
    uint32_t off = (uint32_t)((((lane & 15)) * sp + (lane >> 4) * 8) * 2);
    uint32_t ah0 = aHiA + off, al0 = aLoA + off;
    const uint4* bp[NTW];
#pragma unroll
    for (int j = 0; j < NTW; j++)
        bp[j] = reinterpret_cast<const uint4*>(
                    g_wpack + (long)(blkBase + (wc + 8 * j) * ktStride) * 256) + lane;
    uint4 bc[NTW];
#pragma unroll
    for (int j = 0; j < NTW; j++) bc[j] = bp[j][0];
#pragma unroll 1
    for (int kt = 0; kt < KT; kt++) {
        uint32_t ah[4], al[4];
        ldsm4(ah0 + kt * 32, ah);
        ldsm4(al0 + kt * 32, al);
        uint4 bn[NTW];
        if (kt + 1 < KT) {
#pragma unroll
            for (int j = 0; j < NTW; j++) bn[j] = bp[j][(kt + 1) * 32];
        }
#pragma unroll
        for (int j = 0; j < NTW; j++) {
            hmma(D[j], ah, bc[j].x, bc[j].y);   // Ahi*Bhi
            hmma(D[j], ah, bc[j].z, bc[j].w);   // Ahi*Blo
            hmma(D[j], al, bc[j].x, bc[j].y);   // Alo*Bhi
        }
#pragma unroll
        for (int j = 0; j < NTW; j++) bc[j] = bn[j];
    }
}

// epilogue: +bias (+lrelu) -> hi/lo bf16 region (16 rows)
template <int NTW, bool RELU>
__device__ __forceinline__ void epi_bf(
    float D[4][4], const float* bias, bf16* dHi, bf16* dLo,
    int sp, int wc, int lane)
{
    int r0 = lane >> 2, c0 = (lane & 3) * 2;
#pragma unroll
    for (int j = 0; j < NTW; j++) {
        int col = (wc + 8 * j) * 8 + c0;
        float b0 = bias[col], b1 = bias[col + 1];
#pragma unroll
        for (int h = 0; h < 2; h++) {
            int row = r0 + h * 8;
            float v0 = D[j][2 * h] + b0, v1 = D[j][2 * h + 1] + b1;
            if (RELU) { v0 = lrelu(v0); v1 = lrelu(v1); }
            bf16 h0 = __float2bfloat16(v0), h1 = __float2bfloat16(v1);
            bf16 g0 = __float2bfloat16(v0 - __bfloat162float(h0));
            bf16 g1 = __float2bfloat16(v1 - __bfloat162float(h1));
            *(uint32_t*)(dHi + row * sp + col) =
                ((uint32_t)__bfloat16_as_ushort(h1) << 16) | __bfloat16_as_ushort(h0);
            *(uint32_t*)(dLo + row * sp + col) =
                ((uint32_t)__bfloat16_as_ushort(g1) << 16) | __bfloat16_as_ushort(g0);
        }
    }
}

// smem byte offsets (16-row tiles)
#define O_RINH 0
#define O_RINL 8448
#define O_RGLH 16896
#define O_RGLL 21248
#define O_RAH  25600
#define O_RAL  42240
#define O_RBH  58880
#define O_RBL  67328
#define O_RCH  75776
#define O_RCL  84224
#define O_WG   92672
#define O_GATE 100864
#define O_SUM1 101376
#define O_SUM2 102656
#define O_ACT  103936
#define O_PS   105216
#define SMEM_BYTES 108032

__global__ __launch_bounds__(THREADS, 2) void actor_kernel(
    const float* __restrict__ obs, const float* __restrict__ actions,
    const float* __restrict__ b1, const float* __restrict__ b2,
    const float* __restrict__ bp1, const float* __restrict__ bp2,
    const float* __restrict__ bs1, const float* __restrict__ bs2,
    const float* __restrict__ bs3, const float* __restrict__ bg1,
    const float* __restrict__ bg2, const float* __restrict__ bg3,
    const float* __restrict__ Wgate, const float* __restrict__ bgate,
    float* __restrict__ out)
{
    extern __shared__ char sm[];
    bf16* RINh = (bf16*)(sm + O_RINH); bf16* RINl = (bf16*)(sm + O_RINL);
    bf16* RGLh = (bf16*)(sm + O_RGLH); bf16* RGLl = (bf16*)(sm + O_RGLL);
    bf16* RAh  = (bf16*)(sm + O_RAH);  bf16* RAl  = (bf16*)(sm + O_RAL);
    bf16* RBh  = (bf16*)(sm + O_RBH);  bf16* RBl  = (bf16*)(sm + O_RBL);
    bf16* RCh  = (bf16*)(sm + O_RCH);  bf16* RCl  = (bf16*)(sm + O_RCL);
    float* sWg   = (float*)(sm + O_WG);
    float* sGate = (float*)(sm + O_GATE);
    float* sSum1 = (float*)(sm + O_SUM1);
    float* sSum2 = (float*)(sm + O_SUM2);
    float* sAct  = (float*)(sm + O_ACT);
    float* sPS   = (float*)(sm + O_PS);

    const uint32_t RINhA = s2u(RINh), RINlA = s2u(RINl);
    const uint32_t RGLhA = s2u(RGLh), RGLlA = s2u(RGLl);
    const uint32_t RAhA  = s2u(RAh),  RAlA  = s2u(RAl);
    const uint32_t RBhA  = s2u(RBh),  RBlA  = s2u(RBl);
    const uint32_t RChA  = s2u(RCh),  RClA  = s2u(RCl);

    const int t = threadIdx.x;
    const int lane = t & 31, wc = t >> 5;   // 8 warps, one mtile (16 rows)
    const int rowBase = blockIdx.x * 16;

    // ---- inputs -> hi/lo bf16, misc staging ----
    for (int i = t; i < 16 * 96; i += THREADS) {
        int b = i / 96, c4 = i % 96;
        float4 v = *reinterpret_cast<const float4*>(obs + (size_t)(rowBase + b) * 384 + c4 * 4);
        bf16 *ph, *pl;
        int c;
        if (c4 < 64) { c = c4 * 4; ph = RINh + b * 264 + c; pl = RINl + b * 264 + c; }
        else         { c = (c4 - 64) * 4; ph = RGLh + b * 136 + c; pl = RGLl + b * 136 + c; }
        float vv[4] = {v.x, v.y, v.z, v.w};
#pragma unroll
        for (int q = 0; q < 4; q++) {
            bf16 h = __float2bfloat16(vv[q]);
            ph[q] = h;
            pl[q] = __float2bfloat16(vv[q] - __bfloat162float(h));
        }
    }
    for (int i = t; i < 320; i += THREADS) {
        sAct[i] = actions[(size_t)rowBase * 20 + i];
        sSum1[i] = 0.f; sSum2[i] = 0.f;
    }
    for (int i = t; i < 2048; i += THREADS) sWg[i] = Wgate[i];
    __syncthreads();

    float D[4][4];
    // ---- gate path ----
    zeroD(D); mma_pass<4,16>(D, 6784,      16, RINhA, RINlA, 264, wc, lane);
    epi_bf<4,true>(D, bs1,       RAh,       RAl,       520, wc, lane);
    zeroD(D); mma_pass<4,16>(D, 6784+512,  16, RINhA, RINlA, 264, wc, lane);
    epi_bf<4,true>(D, bs1 + 256, RAh + 256, RAl + 256, 520, wc, lane);
    __syncthreads();
    zeroD(D); mma_pass<4,32>(D, 7808, 32, RAhA, RAlA, 520, wc, lane);
    epi_bf<4,true>(D, bs2, RBh, RBl, 264, wc, lane);
    __syncthreads();
    zeroD(D); mma_pass<2,16>(D, 8832, 16, RBhA, RBlA, 264, wc, lane);
    epi_bf<2,true>(D, bs3, RCh, RCl, 264, wc, lane);      // sg[:,0:128]
    zeroD(D); mma_pass<4,8>(D, 9088,      8, RGLhA, RGLlA, 136, wc, lane);
    epi_bf<4,true>(D, bg1,       RAh,       RAl,       520, wc, lane);
    zeroD(D); mma_pass<4,8>(D, 9088+256,  8, RGLhA, RGLlA, 136, wc, lane);
    epi_bf<4,true>(D, bg1 + 256, RAh + 256, RAl + 256, 520, wc, lane);
    __syncthreads();
    zeroD(D); mma_pass<4,32>(D, 9600, 32, RAhA, RAlA, 520, wc, lane);
    epi_bf<4,true>(D, bg2, RBh, RBl, 264, wc, lane);
    __syncthreads();
    zeroD(D); mma_pass<2,16>(D, 10624, 16, RBhA, RBlA, 264, wc, lane);
    epi_bf<2,true>(D, bg3, RCh + 128, RCl + 128, 264, wc, lane);  // sg[:,128:256]
    __syncthreads();

    // ---- gate: w_gate[b][p] = exp(sg[b].Wgate[:,p] + bgate[p]) ----
    if (t < 128) {
        int b = t >> 3, p = t & 7;
        float acc = 0.f;
        for (int k = 0; k < 256; k++) {
            float s = __bfloat162float(RCh[b * 264 + k]) + __bfloat162float(RCl[b * 264 + k]);
            acc += s * sWg[k * 8 + p];
        }
        sGate[t] = expf(acc + bgate[p]);
    }

    // ---- primitive trunk ----
    zeroD(D); mma_pass<4,16>(D, 0,   16, RINhA, RINlA, 264, wc, lane);
    epi_bf<4,true>(D, b1,       RAh,       RAl,       520, wc, lane);
    zeroD(D); mma_pass<4,16>(D, 512, 16, RINhA, RINlA, 264, wc, lane);
    epi_bf<4,true>(D, b1 + 256, RAh + 256, RAl + 256, 520, wc, lane);
    __syncthreads();
    zeroD(D); mma_pass<4,32>(D, 1024, 32, RAhA, RAlA, 520, wc, lane);
    epi_bf<4,true>(D, b2, RBh, RBl, 264, wc, lane);   // s1 stays in RB
    __syncthreads();

    for (int p = 0; p < 8; p++) {
        zeroD(D); mma_pass<4,16>(D, 2048 + p * 512, 16, RBhA, RBlA, 264, wc, lane);
        epi_bf<4,true>(D, bp1 + p * 256, RCh, RCl, 264, wc, lane);   // h
        __syncthreads();
        if (wc < 5) {
            zeroD(D); mma_pass<1,16>(D, 6144 + p * 80, 16, RChA, RClA, 264, wc, lane);
            int r0 = lane >> 2, c0 = (lane & 3) * 2;
            int col = wc * 8 + c0;
            float bb0 = bp2[p * 40 + col], bb1 = bp2[p * 40 + col + 1];
#pragma unroll
            for (int h = 0; h < 2; h++) {
                int row = r0 + h * 8;
                sPS[row * 44 + col]     = D[0][2 * h]     + bb0;
                sPS[row * 44 + col + 1] = D[0][2 * h + 1] + bb1;
            }
        }
        __syncthreads();
        for (int i = t; i < 320; i += THREADS) {
            int b = i / 20, a = i % 20;
            float mu  = sPS[b * 44 + a];
            float sig = expf(sPS[b * 44 + 20 + a]);
            float inv = sGate[b * 8 + p] / sig;
            sSum1[i] += mu * inv;
            sSum2[i] += inv;
        }
        __syncthreads();
    }

    // ---- final log_prob / entropy ----
    if (t < 16) {
        int b = t;
        float lp = 0.f, ent = 0.f;
#pragma unroll
        for (int a = 0; a < 20; a++) {
            float s1v = sSum1[b * 20 + a];
            float s2v = sSum2[b * 20 + a];
            float mu = s1v / s2v;
            float z = (sAct[b * 20 + a] - mu) * s2v;
            float ls = -logf(s2v);
            lp  += -0.5f * z * z - ls - LOG_SQRT_2PI;
            ent += 0.5f + LOG_SQRT_2PI + ls;
        }
        size_t row = (size_t)rowBase + b;
        out[row * 2 + 0] = lp;
        out[row * 2 + 1] = ent;
    }
}

extern "C" void kernel_launch(void* const* d_in, const int* in_sizes, int n_in,
                              void* d_out, int out_size)
{
    PrepArgs pa;
    pa.s[0] = (const float*)d_in[2];   // W1
    pa.s[1] = (const float*)d_in[4];   // W2
    pa.s[2] = (const float*)d_in[6];   // Wp1
    pa.s[3] = (const float*)d_in[8];   // Wp2
    pa.s[4] = (const float*)d_in[10];  // Ws1
    pa.s[5] = (const float*)d_in[12];  // Ws2
    pa.s[6] = (const float*)d_in[14];  // Ws3
    pa.s[7] = (const float*)d_in[16];  // Wg1
    pa.s[8] = (const float*)d_in[18];  // Wg2
    pa.s[9] = (const float*)d_in[20];  // Wg3
    prep_kernel<<<(1392640 + 255) / 256, 256>>>(pa);

    cudaFuncSetAttribute(actor_kernel,
                         cudaFuncAttributeMaxDynamicSharedMemorySize, SMEM_BYTES);
    actor_kernel<<<4096, THREADS, SMEM_BYTES>>>(
        (const float*)d_in[0], (const float*)d_in[1],
        (const float*)d_in[3], (const float*)d_in[5],
        (const float*)d_in[7], (const float*)d_in[9],
        (const float*)d_in[11], (const float*)d_in[13],
        (const float*)d_in[15], (const float*)d_in[17],
        (const float*)d_in[19], (const float*)d_in[21],
        (const float*)d_in[22], (const float*)d_in[23],
        (float*)d_out);
}

// round 13
// speedup vs baseline: 1.6878x; 1.1289x over previous
#include <cuda_runtime.h>
#include <cuda_fp16.h>
#include <cstdint>

typedef __half fp16;
#define THREADS 256
#define LOG_SQRT_2PI 0.9189385332046727f

// ---------- packed weights: per (16k x 8n) block, 128 fp16 (B-frag order, single) ----------
__device__ fp16 g_wpack[1392640];   // 10880 blocks * 128

struct LDesc { int K, N, base, sid, soff; };
__constant__ LDesc c_layers[24] = {
    {256,512,0,0,0},{512,256,1024,1,0},
    {256,256,2048,2,0},{256,256,2560,2,65536},{256,256,3072,2,131072},{256,256,3584,2,196608},
    {256,256,4096,2,262144},{256,256,4608,2,327680},{256,256,5120,2,393216},{256,256,5632,2,458752},
    {256,40,6144,3,0},{256,40,6224,3,10240},{256,40,6304,3,20480},{256,40,6384,3,30720},
    {256,40,6464,3,40960},{256,40,6544,3,51200},{256,40,6624,3,61440},{256,40,6704,3,71680},
    {256,512,6784,4,0},{512,256,7808,5,0},{256,128,8832,6,0},
    {128,512,9088,7,0},{512,256,9600,8,0},{256,128,10624,9,0}
};
__constant__ long c_prefix[25] = {
    0,131072,262144,327680,393216,458752,524288,589824,655360,720896,786432,
    796672,806912,817152,827392,837632,847872,858112,868352,
    999424,1130496,1163264,1228800,1359872,1392640
};

struct PrepArgs { const float* s[10]; };

__global__ void prep_kernel(PrepArgs a) {
    long i = (long)blockIdx.x * 256 + threadIdx.x;
    if (i >= 1392640L) return;
    int L = 0;
    while (c_prefix[L + 1] <= i) L++;
    LDesc d = c_layers[L];
    int e = (int)(i - c_prefix[L]);
    int k = e / d.N, n = e % d.N;
    float w = a.s[d.sid][(size_t)d.soff + e];
    int blk = d.base + (n >> 3) * (d.K >> 4) + (k >> 4);
    int r = k & 15;
    int lane = (n & 7) * 4 + ((r & 7) >> 1);
    int sub = (r & 1) + ((r >= 8) ? 2 : 0);
    g_wpack[(long)blk * 128 + lane * 4 + sub] = __float2half_rn(w);
}

// ---------- main kernel helpers ----------
__device__ __forceinline__ uint32_t s2u(const void* p) {
    return (uint32_t)__cvta_generic_to_shared(p);
}
__device__ __forceinline__ void ldsm4(uint32_t a, uint32_t* r) {
    asm volatile("ldmatrix.sync.aligned.m8n8.x4.shared.b16 {%0,%1,%2,%3}, [%4];"
        : "=r"(r[0]), "=r"(r[1]), "=r"(r[2]), "=r"(r[3]) : "r"(a));
}
__device__ __forceinline__ void hmma(float* d, const uint32_t* a, uint32_t b0, uint32_t b1) {
    asm volatile("mma.sync.aligned.m16n8k16.row.col.f32.f16.f16.f32 "
        "{%0,%1,%2,%3}, {%4,%5,%6,%7}, {%8,%9}, {%0,%1,%2,%3};"
        : "+f"(d[0]), "+f"(d[1]), "+f"(d[2]), "+f"(d[3])
        : "r"(a[0]), "r"(a[1]), "r"(a[2]), "r"(a[3]), "r"(b0), "r"(b1));
}
__device__ __forceinline__ float lrelu(float v) { return v > 0.f ? v : 0.01f * v; }
__device__ __forceinline__ void zeroD(float D[4][4]) {
#pragma unroll
    for (int j = 0; j < 4; j++)
#pragma unroll
        for (int i = 0; i < 4; i++) D[j][i] = 0.f;
}

// D[j] += A(region, 16 rows) @ B(ntile = wc + 8j), k-tiles 0..KT-1.
// A hi/lo fp16 (exact), W single fp16: 2 HMMA per tile.
template <int NTW, int KT>
__device__ __forceinline__ void mma_pass(
    float D[4][4], int blkBase, int ktStride,
    uint32_t aHiA, uint32_t aLoA, int sp, int wc, int lane)
{
    uint32_t off = (uint32_t)((((lane & 15)) * sp + (lane >> 4) * 8) * 2);
    uint32_t ah0 = aHiA + off, al0 = aLoA + off;
    const uint2* bp[NTW];
#pragma unroll
    for (int j = 0; j < NTW; j++)
        bp[j] = reinterpret_cast<const uint2*>(
                    g_wpack + (long)(blkBase + (wc + 8 * j) * ktStride) * 128) + lane;
    uint2 bc[NTW];
#pragma unroll
    for (int j = 0; j < NTW; j++) bc[j] = bp[j][0];
#pragma unroll 1
    for (int kt = 0; kt < KT; kt++) {
        uint32_t ah[4], al[4];
        ldsm4(ah0 + kt * 32, ah);
        ldsm4(al0 + kt * 32, al);
        uint2 bn[NTW];
        if (kt + 1 < KT) {
#pragma unroll
            for (int j = 0; j < NTW; j++) bn[j] = bp[j][(kt + 1) * 32];
        }
#pragma unroll
        for (int j = 0; j < NTW; j++) {
            hmma(D[j], ah, bc[j].x, bc[j].y);   // Ahi * W
            hmma(D[j], al, bc[j].x, bc[j].y);   // Alo * W
        }
#pragma unroll
        for (int j = 0; j < NTW; j++) bc[j] = bn[j];
    }
}

// epilogue: +bias (+lrelu) -> hi/lo fp16 region (16 rows)
template <int NTW, bool RELU>
__device__ __forceinline__ void epi_bf(
    float D[4][4], const float* bias, fp16* dHi, fp16* dLo,
    int sp, int wc, int lane)
{
    int r0 = lane >> 2, c0 = (lane & 3) * 2;
#pragma unroll
    for (int j = 0; j < NTW; j++) {
        int col = (wc + 8 * j) * 8 + c0;
        float b0 = bias[col], b1 = bias[col + 1];
#pragma unroll
        for (int h = 0; h < 2; h++) {
            int row = r0 + h * 8;
            float v0 = D[j][2 * h] + b0, v1 = D[j][2 * h + 1] + b1;
            if (RELU) { v0 = lrelu(v0); v1 = lrelu(v1); }
            fp16 h0 = __float2half_rn(v0), h1 = __float2half_rn(v1);
            fp16 g0 = __float2half_rn(v0 - __half2float(h0));
            fp16 g1 = __float2half_rn(v1 - __half2float(h1));
            *(uint32_t*)(dHi + row * sp + col) =
                ((uint32_t)__half_as_ushort(h1) << 16) | __half_as_ushort(h0);
            *(uint32_t*)(dLo + row * sp + col) =
                ((uint32_t)__half_as_ushort(g1) << 16) | __half_as_ushort(g0);
        }
    }
}

// smem byte offsets (16-row tiles)
#define O_RINH 0
#define O_RINL 8448
#define O_RGLH 16896
#define O_RGLL 21248
#define O_RAH  25600
#define O_RAL  42240
#define O_RBH  58880
#define O_RBL  67328
#define O_RCH  75776
#define O_RCL  84224
#define O_WG   92672
#define O_GATE 100864
#define O_SUM1 101376
#define O_SUM2 102656
#define O_ACT  103936
#define O_PS   105216
#define SMEM_BYTES 108032

__global__ __launch_bounds__(THREADS, 2) void actor_kernel(
    const float* __restrict__ obs, const float* __restrict__ actions,
    const float* __restrict__ b1, const float* __restrict__ b2,
    const float* __restrict__ bp1, const float* __restrict__ bp2,
    const float* __restrict__ bs1, const float* __restrict__ bs2,
    const float* __restrict__ bs3, const float* __restrict__ bg1,
    const float* __restrict__ bg2, const float* __restrict__ bg3,
    const float* __restrict__ Wgate, const float* __restrict__ bgate,
    float* __restrict__ out)
{
    extern __shared__ char sm[];
    fp16* RINh = (fp16*)(sm + O_RINH); fp16* RINl = (fp16*)(sm + O_RINL);
    fp16* RGLh = (fp16*)(sm + O_RGLH); fp16* RGLl = (fp16*)(sm + O_RGLL);
    fp16* RAh  = (fp16*)(sm + O_RAH);  fp16* RAl  = (fp16*)(sm + O_RAL);
    fp16* RBh  = (fp16*)(sm + O_RBH);  fp16* RBl  = (fp16*)(sm + O_RBL);
    fp16* RCh  = (fp16*)(sm + O_RCH);  fp16* RCl  = (fp16*)(sm + O_RCL);
    float* sWg   = (float*)(sm + O_WG);
    float* sGate = (float*)(sm + O_GATE);
    float* sSum1 = (float*)(sm + O_SUM1);
    float* sSum2 = (float*)(sm + O_SUM2);
    float* sAct  = (float*)(sm + O_ACT);
    float* sPS   = (float*)(sm + O_PS);

    const uint32_t RINhA = s2u(RINh), RINlA = s2u(RINl);
    const uint32_t RGLhA = s2u(RGLh), RGLlA = s2u(RGLl);
    const uint32_t RAhA  = s2u(RAh),  RAlA  = s2u(RAl);
    const uint32_t RBhA  = s2u(RBh),  RBlA  = s2u(RBl);
    const uint32_t RChA  = s2u(RCh),  RClA  = s2u(RCl);

    const int t = threadIdx.x;
    const int lane = t & 31, wc = t >> 5;   // 8 warps, one mtile (16 rows)
    const int rowBase = blockIdx.x * 16;

    // ---- inputs -> hi/lo fp16, misc staging ----
    for (int i = t; i < 16 * 96; i += THREADS) {
        int b = i / 96, c4 = i % 96;
        float4 v = *reinterpret_cast<const float4*>(obs + (size_t)(rowBase + b) * 384 + c4 * 4);
        fp16 *ph, *pl;
        int c;
        if (c4 < 64) { c = c4 * 4; ph = RINh + b * 264 + c; pl = RINl + b * 264 + c; }
        else         { c = (c4 - 64) * 4; ph = RGLh + b * 136 + c; pl = RGLl + b * 136 + c; }
        float vv[4] = {v.x, v.y, v.z, v.w};
#pragma unroll
        for (int q = 0; q < 4; q++) {
            fp16 h = __float2half_rn(vv[q]);
            ph[q] = h;
            pl[q] = __float2half_rn(vv[q] - __half2float(h));
        }
    }
    for (int i = t; i < 320; i += THREADS) {
        sAct[i] = actions[(size_t)rowBase * 20 + i];
        sSum1[i] = 0.f; sSum2[i] = 0.f;
    }
    for (int i = t; i < 2048; i += THREADS) sWg[i] = Wgate[i];
    __syncthreads();

    float D[4][4];
    // ---- gate path ----
    zeroD(D); mma_pass<4,16>(D, 6784,      16, RINhA, RINlA, 264, wc, lane);
    epi_bf<4,true>(D, bs1,       RAh,       RAl,       520, wc, lane);
    zeroD(D); mma_pass<4,16>(D, 6784+512,  16, RINhA, RINlA, 264, wc, lane);
    epi_bf<4,true>(D, bs1 + 256, RAh + 256, RAl + 256, 520, wc, lane);
    __syncthreads();
    zeroD(D); mma_pass<4,32>(D, 7808, 32, RAhA, RAlA, 520, wc, lane);
    epi_bf<4,true>(D, bs2, RBh, RBl, 264, wc, lane);
    __syncthreads();
    zeroD(D); mma_pass<2,16>(D, 8832, 16, RBhA, RBlA, 264, wc, lane);
    epi_bf<2,true>(D, bs3, RCh, RCl, 264, wc, lane);      // sg[:,0:128]
    zeroD(D); mma_pass<4,8>(D, 9088,      8, RGLhA, RGLlA, 136, wc, lane);
    epi_bf<4,true>(D, bg1,       RAh,       RAl,       520, wc, lane);
    zeroD(D); mma_pass<4,8>(D, 9088+256,  8, RGLhA, RGLlA, 136, wc, lane);
    epi_bf<4,true>(D, bg1 + 256, RAh + 256, RAl + 256, 520, wc, lane);
    __syncthreads();
    zeroD(D); mma_pass<4,32>(D, 9600, 32, RAhA, RAlA, 520, wc, lane);
    epi_bf<4,true>(D, bg2, RBh, RBl, 264, wc, lane);
    __syncthreads();
    zeroD(D); mma_pass<2,16>(D, 10624, 16, RBhA, RBlA, 264, wc, lane);
    epi_bf<2,true>(D, bg3, RCh + 128, RCl + 128, 264, wc, lane);  // sg[:,128:256]
    __syncthreads();

    // ---- gate: w_gate[b][p] = exp(sg[b].Wgate[:,p] + bgate[p]) ----
    if (t < 128) {
        int b = t >> 3, p = t & 7;
        float acc = 0.f;
        for (int k = 0; k < 256; k++) {
            float s = __half2float(RCh[b * 264 + k]) + __half2float(RCl[b * 264 + k]);
            acc += s * sWg[k * 8 + p];
        }
        sGate[t] = expf(acc + bgate[p]);
    }

    // ---- primitive trunk ----
    zeroD(D); mma_pass<4,16>(D, 0,   16, RINhA, RINlA, 264, wc, lane);
    epi_bf<4,true>(D, b1,       RAh,       RAl,       520, wc, lane);
    zeroD(D); mma_pass<4,16>(D, 512, 16, RINhA, RINlA, 264, wc, lane);
    epi_bf<4,true>(D, b1 + 256, RAh + 256, RAl + 256, 520, wc, lane);
    __syncthreads();
    zeroD(D); mma_pass<4,32>(D, 1024, 32, RAhA, RAlA, 520, wc, lane);
    epi_bf<4,true>(D, b2, RBh, RBl, 264, wc, lane);   // s1 stays in RB
    __syncthreads();

    for (int p = 0; p < 8; p++) {
        zeroD(D); mma_pass<4,16>(D, 2048 + p * 512, 16, RBhA, RBlA, 264, wc, lane);
        epi_bf<4,true>(D, bp1 + p * 256, RCh, RCl, 264, wc, lane);   // h
        __syncthreads();
        if (wc < 5) {
            zeroD(D); mma_pass<1,16>(D, 6144 + p * 80, 16, RChA, RClA, 264, wc, lane);
            int r0 = lane >> 2, c0 = (lane & 3) * 2;
            int col = wc * 8 + c0;
            float bb0 = bp2[p * 40 + col], bb1 = bp2[p * 40 + col + 1];
#pragma unroll
            for (int h = 0; h < 2; h++) {
                int row = r0 + h * 8;
                sPS[row * 44 + col]     = D[0][2 * h]     + bb0;
                sPS[row * 44 + col + 1] = D[0][2 * h + 1] + bb1;
            }
        }
        __syncthreads();
        for (int i = t; i < 320; i += THREADS) {
            int b = i / 20, a = i % 20;
            float mu  = sPS[b * 44 + a];
            float sig = expf(sPS[b * 44 + 20 + a]);
            float inv = sGate[b * 8 + p] / sig;
            sSum1[i] += mu * inv;
            sSum2[i] += inv;
        }
        __syncthreads();
    }

    // ---- final log_prob / entropy ----
    if (t < 16) {
        int b = t;
        float lp = 0.f, ent = 0.f;
#pragma unroll
        for (int a = 0; a < 20; a++) {
            float s1v = sSum1[b * 20 + a];
            float s2v = sSum2[b * 20 + a];
            float mu = s1v / s2v;
            float z = (sAct[b * 20 + a] - mu) * s2v;
            float ls = -logf(s2v);
            lp  += -0.5f * z * z - ls - LOG_SQRT_2PI;
            ent += 0.5f + LOG_SQRT_2PI + ls;
        }
        size_t row = (size_t)rowBase + b;
        out[row * 2 + 0] = lp;
        out[row * 2 + 1] = ent;
    }
}

extern "C" void kernel_launch(void* const* d_in, const int* in_sizes, int n_in,
                              void* d_out, int out_size)
{
    PrepArgs pa;
    pa.s[0] = (const float*)d_in[2];   // W1
    pa.s[1] = (const float*)d_in[4];   // W2
    pa.s[2] = (const float*)d_in[6];   // Wp1
    pa.s[3] = (const float*)d_in[8];   // Wp2
    pa.s[4] = (const float*)d_in[10];  // Ws1
    pa.s[5] = (const float*)d_in[12];  // Ws2
    pa.s[6] = (const float*)d_in[14];  // Ws3
    pa.s[7] = (const float*)d_in[16];  // Wg1
    pa.s[8] = (const float*)d_in[18];  // Wg2
    pa.s[9] = (const float*)d_in[20];  // Wg3
    prep_kernel<<<(1392640 + 255) / 256, 256>>>(pa);

    cudaFuncSetAttribute(actor_kernel,
                         cudaFuncAttributeMaxDynamicSharedMemorySize, SMEM_BYTES);
    actor_kernel<<<4096, THREADS, SMEM_BYTES>>>(
        (const float*)d_in[0], (const float*)d_in[1],
        (const float*)d_in[3], (const float*)d_in[5],
        (const float*)d_in[7], (const float*)d_in[9],
        (const float*)d_in[11], (const float*)d_in[13],
        (const float*)d_in[15], (const float*)d_in[17],
        (const float*)d_in[19], (const float*)d_in[21],
        (const float*)d_in[22], (const float*)d_in[23],
        (float*)d_out);
}

// round 14
// speedup vs baseline: 2.5191x; 1.4925x over previous
#include <cuda_runtime.h>
#include <cuda_fp16.h>
#include <cstdint>

typedef __half fp16;
#define THREADS 256
#define LOG_SQRT_2PI 0.9189385332046727f

// ---------- packed weights: per (16k x 8n) block, 128 fp16 (B-frag order) ----------
__device__ fp16 g_wpack[1392640];   // 10880 blocks * 128

struct LDesc { int K, N, base, sid, soff; };
__constant__ LDesc c_layers[24] = {
    {256,512,0,0,0},{512,256,1024,1,0},
    {256,256,2048,2,0},{256,256,2560,2,65536},{256,256,3072,2,131072},{256,256,3584,2,196608},
    {256,256,4096,2,262144},{256,256,4608,2,327680},{256,256,5120,2,393216},{256,256,5632,2,458752},
    {256,40,6144,3,0},{256,40,6224,3,10240},{256,40,6304,3,20480},{256,40,6384,3,30720},
    {256,40,6464,3,40960},{256,40,6544,3,51200},{256,40,6624,3,61440},{256,40,6704,3,71680},
    {256,512,6784,4,0},{512,256,7808,5,0},{256,128,8832,6,0},
    {128,512,9088,7,0},{512,256,9600,8,0},{256,128,10624,9,0}
};
__constant__ long c_prefix[25] = {
    0,131072,262144,327680,393216,458752,524288,589824,655360,720896,786432,
    796672,806912,817152,827392,837632,847872,858112,868352,
    999424,1130496,1163264,1228800,1359872,1392640
};

struct PrepArgs { const float* s[10]; };

__global__ void prep_kernel(PrepArgs a) {
    long i = (long)blockIdx.x * 256 + threadIdx.x;
    if (i >= 1392640L) return;
    int L = 0;
    while (c_prefix[L + 1] <= i) L++;
    LDesc d = c_layers[L];
    int e = (int)(i - c_prefix[L]);
    int k = e / d.N, n = e % d.N;
    float w = a.s[d.sid][(size_t)d.soff + e];
    int blk = d.base + (n >> 3) * (d.K >> 4) + (k >> 4);
    int r = k & 15;
    int lane = (n & 7) * 4 + ((r & 7) >> 1);
    int sub = (r & 1) + ((r >= 8) ? 2 : 0);
    g_wpack[(long)blk * 128 + lane * 4 + sub] = __float2half_rn(w);
}

// ---------- main kernel helpers ----------
__device__ __forceinline__ uint32_t s2u(const void* p) {
    return (uint32_t)__cvta_generic_to_shared(p);
}
__device__ __forceinline__ void ldsm4(uint32_t a, uint32_t* r) {
    asm volatile("ldmatrix.sync.aligned.m8n8.x4.shared.b16 {%0,%1,%2,%3}, [%4];"
        : "=r"(r[0]), "=r"(r[1]), "=r"(r[2]), "=r"(r[3]) : "r"(a));
}
__device__ __forceinline__ void hmma(float* d, const uint32_t* a, uint32_t b0, uint32_t b1) {
    asm volatile("mma.sync.aligned.m16n8k16.row.col.f32.f16.f16.f32 "
        "{%0,%1,%2,%3}, {%4,%5,%6,%7}, {%8,%9}, {%0,%1,%2,%3};"
        : "+f"(d[0]), "+f"(d[1]), "+f"(d[2]), "+f"(d[3])
        : "r"(a[0]), "r"(a[1]), "r"(a[2]), "r"(a[3]), "r"(b0), "r"(b1));
}
__device__ __forceinline__ float lrelu(float v) { return v > 0.f ? v : 0.01f * v; }
__device__ __forceinline__ void zeroD(float D[4][4]) {
#pragma unroll
    for (int j = 0; j < 4; j++)
#pragma unroll
        for (int i = 0; i < 4; i++) D[j][i] = 0.f;
}

// D[j] += A(region, 16 rows, single fp16) @ B(ntile = wc + 8j), k-tiles 0..KT-1.
template <int NTW, int KT>
__device__ __forceinline__ void mma_pass(
    float D[4][4], int blkBase, int ktStride,
    uint32_t aA, int sp, int wc, int lane)
{
    uint32_t off = (uint32_t)((((lane & 15)) * sp + (lane >> 4) * 8) * 2);
    uint32_t a0 = aA + off;
    const uint2* bp[NTW];
#pragma unroll
    for (int j = 0; j < NTW; j++)
        bp[j] = reinterpret_cast<const uint2*>(
                    g_wpack + (long)(blkBase + (wc + 8 * j) * ktStride) * 128) + lane;
    uint2 bc[NTW];
#pragma unroll
    for (int j = 0; j < NTW; j++) bc[j] = bp[j][0];
#pragma unroll 1
    for (int kt = 0; kt < KT; kt++) {
        uint32_t ah[4];
        ldsm4(a0 + kt * 32, ah);
        uint2 bn[NTW];
        if (kt + 1 < KT) {
#pragma unroll
            for (int j = 0; j < NTW; j++) bn[j] = bp[j][(kt + 1) * 32];
        }
#pragma unroll
        for (int j = 0; j < NTW; j++)
            hmma(D[j], ah, bc[j].x, bc[j].y);
#pragma unroll
        for (int j = 0; j < NTW; j++) bc[j] = bn[j];
    }
}

// epilogue: +bias (+lrelu) -> fp16 region (16 rows)
template <int NTW, bool RELU>
__device__ __forceinline__ void epi_bf(
    float D[4][4], const float* bias, fp16* dst,
    int sp, int wc, int lane)
{
    int r0 = lane >> 2, c0 = (lane & 3) * 2;
#pragma unroll
    for (int j = 0; j < NTW; j++) {
        int col = (wc + 8 * j) * 8 + c0;
        float b0 = bias[col], b1 = bias[col + 1];
#pragma unroll
        for (int h = 0; h < 2; h++) {
            int row = r0 + h * 8;
            float v0 = D[j][2 * h] + b0, v1 = D[j][2 * h + 1] + b1;
            if (RELU) { v0 = lrelu(v0); v1 = lrelu(v1); }
            fp16 h0 = __float2half_rn(v0), h1 = __float2half_rn(v1);
            *(uint32_t*)(dst + row * sp + col) =
                ((uint32_t)__half_as_ushort(h1) << 16) | __half_as_ushort(h0);
        }
    }
}

// smem byte offsets (16-row tiles, single fp16 activations)
#define O_RIN  0
#define O_RGL  8448
#define O_RA   12800
#define O_RB   29440
#define O_RC   37888
#define O_WG   46336
#define O_GATE 54528
#define O_SUM1 55040
#define O_SUM2 56320
#define O_ACT  57600
#define O_PS   58880
#define SMEM_BYTES 61696

__global__ __launch_bounds__(THREADS, 3) void actor_kernel(
    const float* __restrict__ obs, const float* __restrict__ actions,
    const float* __restrict__ b1, const float* __restrict__ b2,
    const float* __restrict__ bp1, const float* __restrict__ bp2,
    const float* __restrict__ bs1, const float* __restrict__ bs2,
    const float* __restrict__ bs3, const float* __restrict__ bg1,
    const float* __restrict__ bg2, const float* __restrict__ bg3,
    const float* __restrict__ Wgate, const float* __restrict__ bgate,
    float* __restrict__ out)
{
    extern __shared__ char sm[];
    fp16* RIN = (fp16*)(sm + O_RIN);
    fp16* RGL = (fp16*)(sm + O_RGL);
    fp16* RA  = (fp16*)(sm + O_RA);
    fp16* RB  = (fp16*)(sm + O_RB);
    fp16* RC  = (fp16*)(sm + O_RC);
    float* sWg   = (float*)(sm + O_WG);
    float* sGate = (float*)(sm + O_GATE);
    float* sSum1 = (float*)(sm + O_SUM1);
    float* sSum2 = (float*)(sm + O_SUM2);
    float* sAct  = (float*)(sm + O_ACT);
    float* sPS   = (float*)(sm + O_PS);

    const uint32_t RINA = s2u(RIN), RGLA = s2u(RGL);
    const uint32_t RAA  = s2u(RA),  RBA  = s2u(RB), RCA = s2u(RC);

    const int t = threadIdx.x;
    const int lane = t & 31, wc = t >> 5;   // 8 warps, one mtile (16 rows)
    const int rowBase = blockIdx.x * 16;

    // ---- inputs -> fp16, misc staging ----
    for (int i = t; i < 16 * 96; i += THREADS) {
        int b = i / 96, c4 = i % 96;
        float4 v = *reinterpret_cast<const float4*>(obs + (size_t)(rowBase + b) * 384 + c4 * 4);
        fp16* ph;
        int c;
        if (c4 < 64) { c = c4 * 4; ph = RIN + b * 264 + c; }
        else         { c = (c4 - 64) * 4; ph = RGL + b * 136 + c; }
        ph[0] = __float2half_rn(v.x);
        ph[1] = __float2half_rn(v.y);
        ph[2] = __float2half_rn(v.z);
        ph[3] = __float2half_rn(v.w);
    }
    for (int i = t; i < 320; i += THREADS) {
        sAct[i] = actions[(size_t)rowBase * 20 + i];
        sSum1[i] = 0.f; sSum2[i] = 0.f;
    }
    for (int i = t; i < 2048; i += THREADS) sWg[i] = Wgate[i];
    __syncthreads();

    float D[4][4];
    // ---- gate path ----
    zeroD(D); mma_pass<4,16>(D, 6784,      16, RINA, 264, wc, lane);
    epi_bf<4,true>(D, bs1,       RA,       520, wc, lane);
    zeroD(D); mma_pass<4,16>(D, 6784+512,  16, RINA, 264, wc, lane);
    epi_bf<4,true>(D, bs1 + 256, RA + 256, 520, wc, lane);
    __syncthreads();
    zeroD(D); mma_pass<4,32>(D, 7808, 32, RAA, 520, wc, lane);
    epi_bf<4,true>(D, bs2, RB, 264, wc, lane);
    __syncthreads();
    zeroD(D); mma_pass<2,16>(D, 8832, 16, RBA, 264, wc, lane);
    epi_bf<2,true>(D, bs3, RC, 264, wc, lane);            // sg[:,0:128]
    zeroD(D); mma_pass<4,8>(D, 9088,      8, RGLA, 136, wc, lane);
    epi_bf<4,true>(D, bg1,       RA,       520, wc, lane);
    zeroD(D); mma_pass<4,8>(D, 9088+256,  8, RGLA, 136, wc, lane);
    epi_bf<4,true>(D, bg1 + 256, RA + 256, 520, wc, lane);
    __syncthreads();
    zeroD(D); mma_pass<4,32>(D, 9600, 32, RAA, 520, wc, lane);
    epi_bf<4,true>(D, bg2, RB, 264, wc, lane);
    __syncthreads();
    zeroD(D); mma_pass<2,16>(D, 10624, 16, RBA, 264, wc, lane);
    epi_bf<2,true>(D, bg3, RC + 128, 264, wc, lane);      // sg[:,128:256]
    __syncthreads();

    // ---- gate: w_gate[b][p] = exp(sg[b].Wgate[:,p] + bgate[p]) ----
    if (t < 128) {
        int b = t >> 3, p = t & 7;
        float acc = 0.f;
        for (int k = 0; k < 256; k++)
            acc += __half2float(RC[b * 264 + k]) * sWg[k * 8 + p];
        sGate[t] = expf(acc + bgate[p]);
    }

    // ---- primitive trunk ----
    zeroD(D); mma_pass<4,16>(D, 0,   16, RINA, 264, wc, lane);
    epi_bf<4,true>(D, b1,       RA,       520, wc, lane);
    zeroD(D); mma_pass<4,16>(D, 512, 16, RINA, 264, wc, lane);
    epi_bf<4,true>(D, b1 + 256, RA + 256, 520, wc, lane);
    __syncthreads();
    zeroD(D); mma_pass<4,32>(D, 1024, 32, RAA, 520, wc, lane);
    epi_bf<4,true>(D, b2, RB, 264, wc, lane);   // s1 stays in RB
    __syncthreads();

    for (int p = 0; p < 8; p++) {
        zeroD(D); mma_pass<4,16>(D, 2048 + p * 512, 16, RBA, 264, wc, lane);
        epi_bf<4,true>(D, bp1 + p * 256, RC, 264, wc, lane);   // h
        __syncthreads();
        if (wc < 5) {
            zeroD(D); mma_pass<1,16>(D, 6144 + p * 80, 16, RCA, 264, wc, lane);
            int r0 = lane >> 2, c0 = (lane & 3) * 2;
            int col = wc * 8 + c0;
            float bb0 = bp2[p * 40 + col], bb1 = bp2[p * 40 + col + 1];
#pragma unroll
            for (int h = 0; h < 2; h++) {
                int row = r0 + h * 8;
                sPS[row * 44 + col]     = D[0][2 * h]     + bb0;
                sPS[row * 44 + col + 1] = D[0][2 * h + 1] + bb1;
            }
        }
        __syncthreads();
        for (int i = t; i < 320; i += THREADS) {
            int b = i / 20, a = i % 20;
            float mu  = sPS[b * 44 + a];
            float sig = expf(sPS[b * 44 + 20 + a]);
            float inv = sGate[b * 8 + p] / sig;
            sSum1[i] += mu * inv;
            sSum2[i] += inv;
        }
        __syncthreads();
    }

    // ---- final log_prob / entropy ----
    if (t < 16) {
        int b = t;
        float lp = 0.f, ent = 0.f;
#pragma unroll
        for (int a = 0; a < 20; a++) {
            float s1v = sSum1[b * 20 + a];
            float s2v = sSum2[b * 20 + a];
            float mu = s1v / s2v;
            float z = (sAct[b * 20 + a] - mu) * s2v;
            float ls = -logf(s2v);
            lp  += -0.5f * z * z - ls - LOG_SQRT_2PI;
            ent += 0.5f + LOG_SQRT_2PI + ls;
        }
        size_t row = (size_t)rowBase + b;
        out[row * 2 + 0] = lp;
        out[row * 2 + 1] = ent;
    }
}

extern "C" void kernel_launch(void* const* d_in, const int* in_sizes, int n_in,
                              void* d_out, int out_size)
{
    PrepArgs pa;
    pa.s[0] = (const float*)d_in[2];   // W1
    pa.s[1] = (const float*)d_in[4];   // W2
    pa.s[2] = (const float*)d_in[6];   // Wp1
    pa.s[3] = (const float*)d_in[8];   // Wp2
    pa.s[4] = (const float*)d_in[10];  // Ws1
    pa.s[5] = (const float*)d_in[12];  // Ws2
    pa.s[6] = (const float*)d_in[14];  // Ws3
    pa.s[7] = (const float*)d_in[16];  // Wg1
    pa.s[8] = (const float*)d_in[18];  // Wg2
    pa.s[9] = (const float*)d_in[20];  // Wg3
    prep_kernel<<<(1392640 + 255) / 256, 256>>>(pa);

    cudaFuncSetAttribute(actor_kernel,
                         cudaFuncAttributeMaxDynamicSharedMemorySize, SMEM_BYTES);
    actor_kernel<<<4096, THREADS, SMEM_BYTES>>>(
        (const float*)d_in[0], (const float*)d_in[1],
        (const float*)d_in[3], (const float*)d_in[5],
        (const float*)d_in[7], (const float*)d_in[9],
        (const float*)d_in[11], (const float*)d_in[13],
        (const float*)d_in[15], (const float*)d_in[17],
        (const float*)d_in[19], (const float*)d_in[21],
        (const float*)d_in[22], (const float*)d_in[23],
        (float*)d_out);
}

// round 15
// speedup vs baseline: 3.0071x; 1.1937x over previous
#include <cuda_runtime.h>
#include <cuda_fp16.h>
#include <cstdint>

typedef __half fp16;
#define THREADS 256
#define LOG_SQRT_2PI 0.9189385332046727f

// ---------- packed weights: per (16k x 8n) block, 128 fp16 (B-frag order) ----------
__device__ fp16 g_wpack[1392640];   // 10880 blocks * 128

struct LDesc { int K, N, base, sid, soff; };
__constant__ LDesc c_layers[24] = {
    {256,512,0,0,0},{512,256,1024,1,0},
    {256,256,2048,2,0},{256,256,2560,2,65536},{256,256,3072,2,131072},{256,256,3584,2,196608},
    {256,256,4096,2,262144},{256,256,4608,2,327680},{256,256,5120,2,393216},{256,256,5632,2,458752},
    {256,40,6144,3,0},{256,40,6224,3,10240},{256,40,6304,3,20480},{256,40,6384,3,30720},
    {256,40,6464,3,40960},{256,40,6544,3,51200},{256,40,6624,3,61440},{256,40,6704,3,71680},
    {256,512,6784,4,0},{512,256,7808,5,0},{256,128,8832,6,0},
    {128,512,9088,7,0},{512,256,9600,8,0},{256,128,10624,9,0}
};
__constant__ long c_prefix[25] = {
    0,131072,262144,327680,393216,458752,524288,589824,655360,720896,786432,
    796672,806912,817152,827392,837632,847872,858112,868352,
    999424,1130496,1163264,1228800,1359872,1392640
};

struct PrepArgs { const float* s[10]; };

__global__ void prep_kernel(PrepArgs a) {
    long i = (long)blockIdx.x * 256 + threadIdx.x;
    if (i >= 1392640L) return;
    int L = 0;
    while (c_prefix[L + 1] <= i) L++;
    LDesc d = c_layers[L];
    int e = (int)(i - c_prefix[L]);
    int k = e / d.N, n = e % d.N;
    float w = a.s[d.sid][(size_t)d.soff + e];
    int blk = d.base + (n >> 3) * (d.K >> 4) + (k >> 4);
    int r = k & 15;
    int lane = (n & 7) * 4 + ((r & 7) >> 1);
    int sub = (r & 1) + ((r >= 8) ? 2 : 0);
    g_wpack[(long)blk * 128 + lane * 4 + sub] = __float2half_rn(w);
}

// ---------- main kernel helpers ----------
__device__ __forceinline__ uint32_t s2u(const void* p) {
    return (uint32_t)__cvta_generic_to_shared(p);
}
__device__ __forceinline__ void ldsm4(uint32_t a, uint32_t* r) {
    asm volatile("ldmatrix.sync.aligned.m8n8.x4.shared.b16 {%0,%1,%2,%3}, [%4];"
        : "=r"(r[0]), "=r"(r[1]), "=r"(r[2]), "=r"(r[3]) : "r"(a));
}
__device__ __forceinline__ void hmma(float* d, const uint32_t* a, uint32_t b0, uint32_t b1) {
    asm volatile("mma.sync.aligned.m16n8k16.row.col.f32.f16.f16.f32 "
        "{%0,%1,%2,%3}, {%4,%5,%6,%7}, {%8,%9}, {%0,%1,%2,%3};"
        : "+f"(d[0]), "+f"(d[1]), "+f"(d[2]), "+f"(d[3])
        : "r"(a[0]), "r"(a[1]), "r"(a[2]), "r"(a[3]), "r"(b0), "r"(b1));
}
__device__ __forceinline__ float lrelu(float v) { return v > 0.f ? v : 0.01f * v; }

template <int NTW>
__device__ __forceinline__ void zeroD(float D[2][NTW][4]) {
#pragma unroll
    for (int m = 0; m < 2; m++)
#pragma unroll
        for (int j = 0; j < NTW; j++)
#pragma unroll
            for (int i = 0; i < 4; i++) D[m][j][i] = 0.f;
}

// D[mt][j] += A(region, rows mt*16..mt*16+15) @ B(ntile = wc + 8j), k-tiles 0..KT-1.
// 2 mtiles share each B fragment: 8 HMMA per (2 ldsm + NTW B-LDG).
template <int NTW, int KT>
__device__ __forceinline__ void mma_pass(
    float D[2][NTW][4], int blkBase, int ktStride,
    uint32_t aA, int sp, int wc, int lane)
{
    uint32_t off = (uint32_t)((((lane & 15)) * sp + (lane >> 4) * 8) * 2);
    uint32_t a0 = aA + off;
    uint32_t a1 = a0 + (uint32_t)(16 * sp * 2);
    const uint2* bp[NTW];
#pragma unroll
    for (int j = 0; j < NTW; j++)
        bp[j] = reinterpret_cast<const uint2*>(
                    g_wpack + (long)(blkBase + (wc + 8 * j) * ktStride) * 128) + lane;
    uint2 bc[NTW];
#pragma unroll
    for (int j = 0; j < NTW; j++) bc[j] = bp[j][0];
#pragma unroll 1
    for (int kt = 0; kt < KT; kt++) {
        uint32_t am0[4], am1[4];
        ldsm4(a0 + kt * 32, am0);
        ldsm4(a1 + kt * 32, am1);
        uint2 bn[NTW];
        if (kt + 1 < KT) {
#pragma unroll
            for (int j = 0; j < NTW; j++) bn[j] = bp[j][(kt + 1) * 32];
        }
#pragma unroll
        for (int j = 0; j < NTW; j++) {
            hmma(D[0][j], am0, bc[j].x, bc[j].y);
            hmma(D[1][j], am1, bc[j].x, bc[j].y);
        }
#pragma unroll
        for (int j = 0; j < NTW; j++) bc[j] = bn[j];
    }
}

// epilogue: +bias (+lrelu) -> fp16 region (32 rows, both mtiles)
template <int NTW, bool RELU>
__device__ __forceinline__ void epi_bf(
    float D[2][NTW][4], const float* bias, fp16* dst,
    int sp, int wc, int lane)
{
    int r0 = lane >> 2, c0 = (lane & 3) * 2;
#pragma unroll
    for (int j = 0; j < NTW; j++) {
        int col = (wc + 8 * j) * 8 + c0;
        float b0 = bias[col], b1 = bias[col + 1];
#pragma unroll
        for (int m = 0; m < 2; m++) {
#pragma unroll
            for (int h = 0; h < 2; h++) {
                int row = m * 16 + r0 + h * 8;
                float v0 = D[m][j][2 * h] + b0, v1 = D[m][j][2 * h + 1] + b1;
                if (RELU) { v0 = lrelu(v0); v1 = lrelu(v1); }
                fp16 h0 = __float2half_rn(v0), h1 = __float2half_rn(v1);
                *(uint32_t*)(dst + row * sp + col) =
                    ((uint32_t)__half_as_ushort(h1) << 16) | __half_as_ushort(h0);
            }
        }
    }
}

// smem byte offsets (32-row tiles, single fp16 activations)
#define O_RIN  0        // 32*264*2 = 16896
#define O_RGL  16896    // 32*136*2 = 8704
#define O_RA   25600    // 32*520*2 = 33280
#define O_RB   58880    // 32*264*2 = 16896
#define O_RC   75776    // 32*264*2 = 16896
#define O_WG   92672    // 2048 fp16 = 4096
#define O_GATE 96768    // 256*4 = 1024
#define O_SUM1 97792    // 640*4 = 2560
#define O_SUM2 100352   // 2560
#define O_ACT  102912   // 2560
#define O_PS   105472   // 32*44*4 = 5632
#define SMEM_BYTES 111104

__global__ __launch_bounds__(THREADS, 2) void actor_kernel(
    const float* __restrict__ obs, const float* __restrict__ actions,
    const float* __restrict__ b1, const float* __restrict__ b2,
    const float* __restrict__ bp1, const float* __restrict__ bp2,
    const float* __restrict__ bs1, const float* __restrict__ bs2,
    const float* __restrict__ bs3, const float* __restrict__ bg1,
    const float* __restrict__ bg2, const float* __restrict__ bg3,
    const float* __restrict__ Wgate, const float* __restrict__ bgate,
    float* __restrict__ out)
{
    extern __shared__ char sm[];
    fp16* RIN = (fp16*)(sm + O_RIN);
    fp16* RGL = (fp16*)(sm + O_RGL);
    fp16* RA  = (fp16*)(sm + O_RA);
    fp16* RB  = (fp16*)(sm + O_RB);
    fp16* RC  = (fp16*)(sm + O_RC);
    fp16*  sWg   = (fp16*)(sm + O_WG);
    float* sGate = (float*)(sm + O_GATE);
    float* sSum1 = (float*)(sm + O_SUM1);
    float* sSum2 = (float*)(sm + O_SUM2);
    float* sAct  = (float*)(sm + O_ACT);
    float* sPS   = (float*)(sm + O_PS);

    const uint32_t RINA = s2u(RIN), RGLA = s2u(RGL);
    const uint32_t RAA  = s2u(RA),  RBA  = s2u(RB), RCA = s2u(RC);

    const int t = threadIdx.x;
    const int lane = t & 31, wc = t >> 5;   // 8 warps; each owns 2 mtiles (32 rows)
    const int rowBase = blockIdx.x * 32;

    // ---- inputs -> fp16, misc staging ----
    for (int i = t; i < 32 * 96; i += THREADS) {
        int b = i / 96, c4 = i % 96;
        float4 v = *reinterpret_cast<const float4*>(obs + (size_t)(rowBase + b) * 384 + c4 * 4);
        fp16* ph;
        int c;
        if (c4 < 64) { c = c4 * 4; ph = RIN + b * 264 + c; }
        else         { c = (c4 - 64) * 4; ph = RGL + b * 136 + c; }
        ph[0] = __float2half_rn(v.x);
        ph[1] = __float2half_rn(v.y);
        ph[2] = __float2half_rn(v.z);
        ph[3] = __float2half_rn(v.w);
    }
    for (int i = t; i < 640; i += THREADS) {
        sAct[i] = actions[(size_t)rowBase * 20 + i];
        sSum1[i] = 0.f; sSum2[i] = 0.f;
    }
    for (int i = t; i < 2048; i += THREADS) sWg[i] = __float2half_rn(Wgate[i]);
    __syncthreads();

    float D[2][4][4];
    float (*D2)[2][4] = reinterpret_cast<float (*)[2][4]>(D);  // view for NTW=2
    float (*D1)[1][4] = reinterpret_cast<float (*)[1][4]>(D);  // view for NTW=1

    // ---- gate path ----
    zeroD<4>(D); mma_pass<4,16>(D, 6784,      16, RINA, 264, wc, lane);
    epi_bf<4,true>(D, bs1,       RA,       520, wc, lane);
    zeroD<4>(D); mma_pass<4,16>(D, 6784+512,  16, RINA, 264, wc, lane);
    epi_bf<4,true>(D, bs1 + 256, RA + 256, 520, wc, lane);
    __syncthreads();
    zeroD<4>(D); mma_pass<4,32>(D, 7808, 32, RAA, 520, wc, lane);
    epi_bf<4,true>(D, bs2, RB, 264, wc, lane);
    __syncthreads();
    zeroD<4>(D); mma_pass<2,16>(*(float (*)[2][2][4])&D2[0], 8832, 16, RBA, 264, wc, lane);
    epi_bf<2,true>(*(float (*)[2][2][4])&D2[0], bs3, RC, 264, wc, lane);   // sg[:,0:128]
    zeroD<4>(D); mma_pass<4,8>(D, 9088,      8, RGLA, 136, wc, lane);
    epi_bf<4,true>(D, bg1,       RA,       520, wc, lane);
    zeroD<4>(D); mma_pass<4,8>(D, 9088+256,  8, RGLA, 136, wc, lane);
    epi_bf<4,true>(D, bg1 + 256, RA + 256, 520, wc, lane);
    __syncthreads();
    zeroD<4>(D); mma_pass<4,32>(D, 9600, 32, RAA, 520, wc, lane);
    epi_bf<4,true>(D, bg2, RB, 264, wc, lane);
    __syncthreads();
    zeroD<4>(D); mma_pass<2,16>(*(float (*)[2][2][4])&D2[0], 10624, 16, RBA, 264, wc, lane);
    epi_bf<2,true>(*(float (*)[2][2][4])&D2[0], bg3, RC + 128, 264, wc, lane);  // sg[:,128:256]
    __syncthreads();

    // ---- gate: w_gate[b][p] = exp(sg[b].Wgate[:,p] + bgate[p]) ----
    {
        int b = t >> 3, p = t & 7;
        float acc = 0.f;
        for (int k = 0; k < 256; k++)
            acc += __half2float(RC[b * 264 + k]) * __half2float(sWg[k * 8 + p]);
        sGate[t] = expf(acc + bgate[p]);
    }

    // ---- primitive trunk ----
    zeroD<4>(D); mma_pass<4,16>(D, 0,   16, RINA, 264, wc, lane);
    epi_bf<4,true>(D, b1,       RA,       520, wc, lane);
    zeroD<4>(D); mma_pass<4,16>(D, 512, 16, RINA, 264, wc, lane);
    epi_bf<4,true>(D, b1 + 256, RA + 256, 520, wc, lane);
    __syncthreads();
    zeroD<4>(D); mma_pass<4,32>(D, 1024, 32, RAA, 520, wc, lane);
    epi_bf<4,true>(D, b2, RB, 264, wc, lane);   // s1 stays in RB
    __syncthreads();

    for (int p = 0; p < 8; p++) {
        zeroD<4>(D); mma_pass<4,16>(D, 2048 + p * 512, 16, RBA, 264, wc, lane);
        epi_bf<4,true>(D, bp1 + p * 256, RC, 264, wc, lane);   // h
        __syncthreads();
        if (wc < 5) {
            zeroD<4>(D);
            mma_pass<1,16>(*(float (*)[2][1][4])&D1[0], 6144 + p * 80, 16, RCA, 264, wc, lane);
            int r0 = lane >> 2, c0 = (lane & 3) * 2;
            int col = wc * 8 + c0;
            float bb0 = bp2[p * 40 + col], bb1 = bp2[p * 40 + col + 1];
#pragma unroll
            for (int m = 0; m < 2; m++) {
#pragma unroll
                for (int h = 0; h < 2; h++) {
                    int row = m * 16 + r0 + h * 8;
                    sPS[row * 44 + col]     = D1[m][0][2 * h]     + bb0;
                    sPS[row * 44 + col + 1] = D1[m][0][2 * h + 1] + bb1;
                }
            }
        }
        __syncthreads();
        for (int i = t; i < 640; i += THREADS) {
            int b = i / 20, a = i % 20;
            float mu  = sPS[b * 44 + a];
            float sig = expf(sPS[b * 44 + 20 + a]);
            float inv = sGate[b * 8 + p] / sig;
            sSum1[i] += mu * inv;
            sSum2[i] += inv;
        }
        __syncthreads();
    }

    // ---- final log_prob / entropy ----
    if (t < 32) {
        int b = t;
        float lp = 0.f, ent = 0.f;
#pragma unroll
        for (int a = 0; a < 20; a++) {
            float s1v = sSum1[b * 20 + a];
            float s2v = sSum2[b * 20 + a];
            float mu = s1v / s2v;
            float z = (sAct[b * 20 + a] - mu) * s2v;
            float ls = -logf(s2v);
            lp  += -0.5f * z * z - ls - LOG_SQRT_2PI;
            ent += 0.5f + LOG_SQRT_2PI + ls;
        }
        size_t row = (size_t)rowBase + b;
        out[row * 2 + 0] = lp;
        out[row * 2 + 1] = ent;
    }
}

extern "C" void kernel_launch(void* const* d_in, const int* in_sizes, int n_in,
                              void* d_out, int out_size)
{
    PrepArgs pa;
    pa.s[0] = (const float*)d_in[2];   // W1
    pa.s[1] = (const float*)d_in[4];   // W2
    pa.s[2] = (const float*)d_in[6];   // Wp1
    pa.s[3] = (const float*)d_in[8];   // Wp2
    pa.s[4] = (const float*)d_in[10];  // Ws1
    pa.s[5] = (const float*)d_in[12];  // Ws2
    pa.s[6] = (const float*)d_in[14];  // Ws3
    pa.s[7] = (const float*)d_in[16];  // Wg1
    pa.s[8] = (const float*)d_in[18];  // Wg2
    pa.s[9] = (const float*)d_in[20];  // Wg3
    prep_kernel<<<(1392640 + 255) / 256, 256>>>(pa);

    cudaFuncSetAttribute(actor_kernel,
                         cudaFuncAttributeMaxDynamicSharedMemorySize, SMEM_BYTES);
    actor_kernel<<<2048, THREADS, SMEM_BYTES>>>(
        (const float*)d_in[0], (const float*)d_in[1],
        (const float*)d_in[3], (const float*)d_in[5],
        (const float*)d_in[7], (const float*)d_in[9],
        (const float*)d_in[11], (const float*)d_in[13],
        (const float*)d_in[15], (const float*)d_in[17],
        (const float*)d_in[19], (const float*)d_in[21],
        (const float*)d_in[22], (const float*)d_in[23],
        (float*)d_out);
}

// round 16
// speedup vs baseline: 4.3684x; 1.4527x over previous
#include <cuda_runtime.h>
#include <cuda_fp16.h>
#include <cstdint>

typedef __half fp16;
#define THREADS 256
#define LOG_SQRT_2PI 0.9189385332046727f

// ---------- packed weights: per (16k x 8n) block, 128 fp16 (B-frag order) ----------
__device__ fp16 g_wpack[1392640];   // 10880 blocks * 128

struct LDesc { int K, N, base, sid, soff; };
__constant__ LDesc c_layers[24] = {
    {256,512,0,0,0},{512,256,1024,1,0},
    {256,256,2048,2,0},{256,256,2560,2,65536},{256,256,3072,2,131072},{256,256,3584,2,196608},
    {256,256,4096,2,262144},{256,256,4608,2,327680},{256,256,5120,2,393216},{256,256,5632,2,458752},
    {256,40,6144,3,0},{256,40,6224,3,10240},{256,40,6304,3,20480},{256,40,6384,3,30720},
    {256,40,6464,3,40960},{256,40,6544,3,51200},{256,40,6624,3,61440},{256,40,6704,3,71680},
    {256,512,6784,4,0},{512,256,7808,5,0},{256,128,8832,6,0},
    {128,512,9088,7,0},{512,256,9600,8,0},{256,128,10624,9,0}
};
__constant__ long c_prefix[25] = {
    0,131072,262144,327680,393216,458752,524288,589824,655360,720896,786432,
    796672,806912,817152,827392,837632,847872,858112,868352,
    999424,1130496,1163264,1228800,1359872,1392640
};

struct PrepArgs { const float* s[10]; };

__global__ void prep_kernel(PrepArgs a) {
    long i = (long)blockIdx.x * 256 + threadIdx.x;
    if (i >= 1392640L) return;
    int L = 0;
    while (c_prefix[L + 1] <= i) L++;
    LDesc d = c_layers[L];
    int e = (int)(i - c_prefix[L]);
    int k = e / d.N, n = e % d.N;
    float w = a.s[d.sid][(size_t)d.soff + e];
    int blk = d.base + (n >> 3) * (d.K >> 4) + (k >> 4);
    int r = k & 15;
    int lane = (n & 7) * 4 + ((r & 7) >> 1);
    int sub = (r & 1) + ((r >= 8) ? 2 : 0);
    g_wpack[(long)blk * 128 + lane * 4 + sub] = __float2half_rn(w);
}

// ---------- main kernel helpers ----------
__device__ __forceinline__ uint32_t s2u(const void* p) {
    return (uint32_t)__cvta_generic_to_shared(p);
}
__device__ __forceinline__ void ldsm4(uint32_t a, uint32_t* r) {
    asm volatile("ldmatrix.sync.aligned.m8n8.x4.shared.b16 {%0,%1,%2,%3}, [%4];"
        : "=r"(r[0]), "=r"(r[1]), "=r"(r[2]), "=r"(r[3]) : "r"(a));
}
__device__ __forceinline__ void hmma(float* d, const uint32_t* a, uint32_t b0, uint32_t b1) {
    asm volatile("mma.sync.aligned.m16n8k16.row.col.f32.f16.f16.f32 "
        "{%0,%1,%2,%3}, {%4,%5,%6,%7}, {%8,%9}, {%0,%1,%2,%3};"
        : "+f"(d[0]), "+f"(d[1]), "+f"(d[2]), "+f"(d[3])
        : "r"(a[0]), "r"(a[1]), "r"(a[2]), "r"(a[3]), "r"(b0), "r"(b1));
}
__device__ __forceinline__ float lrelu(float v) { return v > 0.f ? v : 0.01f * v; }

template <int NTW>
__device__ __forceinline__ void zeroD(float D[2][NTW][4]) {
#pragma unroll
    for (int m = 0; m < 2; m++)
#pragma unroll
        for (int j = 0; j < NTW; j++)
#pragma unroll
            for (int i = 0; i < 4; i++) D[m][j][i] = 0.f;
}

// D[mt][j] += A(region, rows mt*16..) @ B(ntile = wc + 8j), k-tiles 0..KT-1.
// B prefetched through a PF=4 deep register ring (covers L2 latency).
template <int NTW, int KT>
__device__ __forceinline__ void mma_pass(
    float D[2][NTW][4], int blkBase, int ktStride,
    uint32_t aA, int sp, int wc, int lane)
{
    constexpr int PF = (KT < 4) ? KT : 4;
    uint32_t off = (uint32_t)((((lane & 15)) * sp + (lane >> 4) * 8) * 2);
    uint32_t a0 = aA + off;
    uint32_t a1 = a0 + (uint32_t)(16 * sp * 2);
    const uint2* bp[NTW];
#pragma unroll
    for (int j = 0; j < NTW; j++)
        bp[j] = reinterpret_cast<const uint2*>(
                    g_wpack + (long)(blkBase + (wc + 8 * j) * ktStride) * 128) + lane;
    uint2 bb[PF][NTW];
#pragma unroll
    for (int s = 0; s < PF; s++)
#pragma unroll
        for (int j = 0; j < NTW; j++)
            bb[s][j] = bp[j][s * 32];
#pragma unroll 4
    for (int kt = 0; kt < KT; kt++) {
        const int c = kt % PF;
        uint32_t am0[4], am1[4];
        ldsm4(a0 + kt * 32, am0);
        ldsm4(a1 + kt * 32, am1);
#pragma unroll
        for (int j = 0; j < NTW; j++) {
            hmma(D[0][j], am0, bb[c][j].x, bb[c][j].y);
            hmma(D[1][j], am1, bb[c][j].x, bb[c][j].y);
        }
        if (kt + PF < KT) {
#pragma unroll
            for (int j = 0; j < NTW; j++) bb[c][j] = bp[j][(kt + PF) * 32];
        }
    }
}

// epilogue: +bias (+lrelu) -> fp16 region (32 rows, both mtiles)
template <int NTW, bool RELU>
__device__ __forceinline__ void epi_bf(
    float D[2][NTW][4], const float* bias, fp16* dst,
    int sp, int wc, int lane)
{
    int r0 = lane >> 2, c0 = (lane & 3) * 2;
#pragma unroll
    for (int j = 0; j < NTW; j++) {
        int col = (wc + 8 * j) * 8 + c0;
        float b0 = bias[col], b1 = bias[col + 1];
#pragma unroll
        for (int m = 0; m < 2; m++) {
#pragma unroll
            for (int h = 0; h < 2; h++) {
                int row = m * 16 + r0 + h * 8;
                float v0 = D[m][j][2 * h] + b0, v1 = D[m][j][2 * h + 1] + b1;
                if (RELU) { v0 = lrelu(v0); v1 = lrelu(v1); }
                fp16 h0 = __float2half_rn(v0), h1 = __float2half_rn(v1);
                *(uint32_t*)(dst + row * sp + col) =
                    ((uint32_t)__half_as_ushort(h1) << 16) | __half_as_ushort(h0);
            }
        }
    }
}

// smem byte offsets (32-row tiles, single fp16 activations)
#define O_RIN  0        // 32*264*2 = 16896
#define O_RGL  16896    // 32*136*2 = 8704
#define O_RA   25600    // 32*520*2 = 33280
#define O_RB   58880    // 32*264*2 = 16896
#define O_RC   75776    // 32*264*2 = 16896
#define O_WG   92672    // 2048 fp16 = 4096
#define O_GATE 96768    // 256*4 = 1024
#define O_SUM1 97792    // 640*4 = 2560
#define O_SUM2 100352   // 2560
#define O_ACT  102912   // 2560
#define O_PS   105472   // 32*44*4 = 5632
#define SMEM_BYTES 111104

__global__ __launch_bounds__(THREADS, 2) void actor_kernel(
    const float* __restrict__ obs, const float* __restrict__ actions,
    const float* __restrict__ b1, const float* __restrict__ b2,
    const float* __restrict__ bp1, const float* __restrict__ bp2,
    const float* __restrict__ bs1, const float* __restrict__ bs2,
    const float* __restrict__ bs3, const float* __restrict__ bg1,
    const float* __restrict__ bg2, const float* __restrict__ bg3,
    const float* __restrict__ Wgate, const float* __restrict__ bgate,
    float* __restrict__ out)
{
    extern __shared__ char sm[];
    fp16* RIN = (fp16*)(sm + O_RIN);
    fp16* RGL = (fp16*)(sm + O_RGL);
    fp16* RA  = (fp16*)(sm + O_RA);
    fp16* RB  = (fp16*)(sm + O_RB);
    fp16* RC  = (fp16*)(sm + O_RC);
    fp16*  sWg   = (fp16*)(sm + O_WG);
    float* sGate = (float*)(sm + O_GATE);
    float* sSum1 = (float*)(sm + O_SUM1);
    float* sSum2 = (float*)(sm + O_SUM2);
    float* sAct  = (float*)(sm + O_ACT);
    float* sPS   = (float*)(sm + O_PS);

    const uint32_t RINA = s2u(RIN), RGLA = s2u(RGL);
    const uint32_t RAA  = s2u(RA),  RBA  = s2u(RB), RCA = s2u(RC);

    const int t = threadIdx.x;
    const int lane = t & 31, wc = t >> 5;   // 8 warps; each owns 2 mtiles (32 rows)
    const int rowBase = blockIdx.x * 32;

    // ---- inputs -> fp16, misc staging ----
    for (int i = t; i < 32 * 96; i += THREADS) {
        int b = i / 96, c4 = i % 96;
        float4 v = *reinterpret_cast<const float4*>(obs + (size_t)(rowBase + b) * 384 + c4 * 4);
        fp16* ph;
        int c;
        if (c4 < 64) { c = c4 * 4; ph = RIN + b * 264 + c; }
        else         { c = (c4 - 64) * 4; ph = RGL + b * 136 + c; }
        ph[0] = __float2half_rn(v.x);
        ph[1] = __float2half_rn(v.y);
        ph[2] = __float2half_rn(v.z);
        ph[3] = __float2half_rn(v.w);
    }
    for (int i = t; i < 640; i += THREADS) {
        sAct[i] = actions[(size_t)rowBase * 20 + i];
        sSum1[i] = 0.f; sSum2[i] = 0.f;
    }
    for (int i = t; i < 2048; i += THREADS) sWg[i] = __float2half_rn(Wgate[i]);
    __syncthreads();

    float D[2][4][4];
    float (*D2)[2][4] = reinterpret_cast<float (*)[2][4]>(D);  // view for NTW=2
    float (*D1)[1][4] = reinterpret_cast<float (*)[1][4]>(D);  // view for NTW=1

    // ---- gate path ----
    zeroD<4>(D); mma_pass<4,16>(D, 6784,      16, RINA, 264, wc, lane);
    epi_bf<4,true>(D, bs1,       RA,       520, wc, lane);
    zeroD<4>(D); mma_pass<4,16>(D, 6784+512,  16, RINA, 264, wc, lane);
    epi_bf<4,true>(D, bs1 + 256, RA + 256, 520, wc, lane);
    __syncthreads();
    zeroD<4>(D); mma_pass<4,32>(D, 7808, 32, RAA, 520, wc, lane);
    epi_bf<4,true>(D, bs2, RB, 264, wc, lane);
    __syncthreads();
    zeroD<4>(D); mma_pass<2,16>(*(float (*)[2][2][4])&D2[0], 8832, 16, RBA, 264, wc, lane);
    epi_bf<2,true>(*(float (*)[2][2][4])&D2[0], bs3, RC, 264, wc, lane);   // sg[:,0:128]
    zeroD<4>(D); mma_pass<4,8>(D, 9088,      8, RGLA, 136, wc, lane);
    epi_bf<4,true>(D, bg1,       RA,       520, wc, lane);
    zeroD<4>(D); mma_pass<4,8>(D, 9088+256,  8, RGLA, 136, wc, lane);
    epi_bf<4,true>(D, bg1 + 256, RA + 256, 520, wc, lane);
    __syncthreads();
    zeroD<4>(D); mma_pass<4,32>(D, 9600, 32, RAA, 520, wc, lane);
    epi_bf<4,true>(D, bg2, RB, 264, wc, lane);
    __syncthreads();
    zeroD<4>(D); mma_pass<2,16>(*(float (*)[2][2][4])&D2[0], 10624, 16, RBA, 264, wc, lane);
    epi_bf<2,true>(*(float (*)[2][2][4])&D2[0], bg3, RC + 128, 264, wc, lane);  // sg[:,128:256]
    __syncthreads();

    // ---- gate: w_gate[b][p] = exp(sg[b].Wgate[:,p] + bgate[p]) ----
    {
        int b = t >> 3, p = t & 7;
        float acc = 0.f;
        for (int k = 0; k < 256; k++)
            acc += __half2float(RC[b * 264 + k]) * __half2float(sWg[k * 8 + p]);
        sGate[t] = expf(acc + bgate[p]);
    }

    // ---- primitive trunk ----
    zeroD<4>(D); mma_pass<4,16>(D, 0,   16, RINA, 264, wc, lane);
    epi_bf<4,true>(D, b1,       RA,       520, wc, lane);
    zeroD<4>(D); mma_pass<4,16>(D, 512, 16, RINA, 264, wc, lane);
    epi_bf<4,true>(D, b1 + 256, RA + 256, 520, wc, lane);
    __syncthreads();
    zeroD<4>(D); mma_pass<4,32>(D, 1024, 32, RAA, 520, wc, lane);
    epi_bf<4,true>(D, b2, RB, 264, wc, lane);   // s1 stays in RB
    __syncthreads();

    for (int p = 0; p < 8; p++) {
        zeroD<4>(D); mma_pass<4,16>(D, 2048 + p * 512, 16, RBA, 264, wc, lane);
        epi_bf<4,true>(D, bp1 + p * 256, RC, 264, wc, lane);   // h
        __syncthreads();
        if (wc < 5) {
            zeroD<4>(D);
            mma_pass<1,16>(*(float (*)[2][1][4])&D1[0], 6144 + p * 80, 16, RCA, 264, wc, lane);
            int r0 = lane >> 2, c0 = (lane & 3) * 2;
            int col = wc * 8 + c0;
            float bb0 = bp2[p * 40 + col], bb1 = bp2[p * 40 + col + 1];
#pragma unroll
            for (int m = 0; m < 2; m++) {
#pragma unroll
                for (int h = 0; h < 2; h++) {
                    int row = m * 16 + r0 + h * 8;
                    sPS[row * 44 + col]     = D1[m][0][2 * h]     + bb0;
                    sPS[row * 44 + col + 1] = D1[m][0][2 * h + 1] + bb1;
                }
            }
        }
        __syncthreads();
        for (int i = t; i < 640; i += THREADS) {
            int b = i / 20, a = i % 20;
            float mu  = sPS[b * 44 + a];
            float sig = expf(sPS[b * 44 + 20 + a]);
            float inv = sGate[b * 8 + p] / sig;
            sSum1[i] += mu * inv;
            sSum2[i] += inv;
        }
        __syncthreads();
    }

    // ---- final log_prob / entropy ----
    if (t < 32) {
        int b = t;
        float lp = 0.f, ent = 0.f;
#pragma unroll
        for (int a = 0; a < 20; a++) {
            float s1v = sSum1[b * 20 + a];
            float s2v = sSum2[b * 20 + a];
            float mu = s1v / s2v;
            float z = (sAct[b * 20 + a] - mu) * s2v;
            float ls = -logf(s2v);
            lp  += -0.5f * z * z - ls - LOG_SQRT_2PI;
            ent += 0.5f + LOG_SQRT_2PI + ls;
        }
        size_t row = (size_t)rowBase + b;
        out[row * 2 + 0] = lp;
        out[row * 2 + 1] = ent;
    }
}

extern "C" void kernel_launch(void* const* d_in, const int* in_sizes, int n_in,
                              void* d_out, int out_size)
{
    PrepArgs pa;
    pa.s[0] = (const float*)d_in[2];   // W1
    pa.s[1] = (const float*)d_in[4];   // W2
    pa.s[2] = (const float*)d_in[6];   // Wp1
    pa.s[3] = (const float*)d_in[8];   // Wp2
    pa.s[4] = (const float*)d_in[10];  // Ws1
    pa.s[5] = (const float*)d_in[12];  // Ws2
    pa.s[6] = (const float*)d_in[14];  // Ws3
    pa.s[7] = (const float*)d_in[16];  // Wg1
    pa.s[8] = (const float*)d_in[18];  // Wg2
    pa.s[9] = (const float*)d_in[20];  // Wg3
    prep_kernel<<<(1392640 + 255) / 256, 256>>>(pa);

    cudaFuncSetAttribute(actor_kernel,
                         cudaFuncAttributeMaxDynamicSharedMemorySize, SMEM_BYTES);
    actor_kernel<<<2048, THREADS, SMEM_BYTES>>>(
        (const float*)d_in[0], (const float*)d_in[1],
        (const float*)d_in[3], (const float*)d_in[5],
        (const float*)d_in[7], (const float*)d_in[9],
        (const float*)d_in[11], (const float*)d_in[13],
        (const float*)d_in[15], (const float*)d_in[17],
        (const float*)d_in[19], (const float*)d_in[21],
        (const float*)d_in[22], (const float*)d_in[23],
        (float*)d_out);
}